// round 2
// baseline (speedup 1.0000x reference)
#include <cuda_runtime.h>
#include <cuda_bf16.h>
#include <math.h>

// ---------------------------------------------------------------------------
// Scratch buffers (device globals; no allocation allowed)
// L=5000, dim=1536 for this problem instance.
// ---------------------------------------------------------------------------
#define MAX_L   5000
#define DIMM    1536
__device__ float g_q[MAX_L * DIMM];
__device__ float g_k[MAX_L * DIMM];
__device__ float g_v[MAX_L * DIMM];
__device__ float g_o[MAX_L * DIMM];

// ---------------------------------------------------------------------------
// GEMM: C[M,N] = A[M,K] @ W[K,N] + bias[N]
// 64x64 block tile, BK=16, 256 threads, 4x4 per-thread microtile.
// ---------------------------------------------------------------------------
__global__ __launch_bounds__(256) void sgemm_bias(
    const float* __restrict__ A, const float* __restrict__ W,
    const float* __restrict__ bias, float* __restrict__ C,
    int M, int N, int K)
{
    __shared__ __align__(16) float As[16][68];   // [k][m], padded
    __shared__ __align__(16) float Ws[16][64];   // [k][n]

    const int tid = threadIdx.x;
    const int tx = tid & 15;
    const int ty = tid >> 4;
    const int m0 = blockIdx.y << 6;
    const int n0 = blockIdx.x << 6;

    const int lmA = tid >> 2;          // 0..63
    const int lkA = (tid & 3) << 2;    // 0,4,8,12
    const int lkW = tid >> 4;          // 0..15
    const int lnW = (tid & 15) << 2;   // 0..60

    float acc[4][4];
#pragma unroll
    for (int i = 0; i < 4; i++)
#pragma unroll
        for (int j = 0; j < 4; j++) acc[i][j] = 0.0f;

    for (int k0 = 0; k0 < K; k0 += 16) {
        float4 av = make_float4(0.f, 0.f, 0.f, 0.f);
        int ar = m0 + lmA;
        if (ar < M)
            av = *(const float4*)(A + (size_t)ar * K + k0 + lkA);
        As[lkA + 0][lmA] = av.x;
        As[lkA + 1][lmA] = av.y;
        As[lkA + 2][lmA] = av.z;
        As[lkA + 3][lmA] = av.w;

        *(float4*)&Ws[lkW][lnW] =
            *(const float4*)(W + (size_t)(k0 + lkW) * N + n0 + lnW);

        __syncthreads();

#pragma unroll
        for (int kk = 0; kk < 16; kk++) {
            float4 a = *(const float4*)&As[kk][ty << 2];
            float4 b = *(const float4*)&Ws[kk][tx << 2];
            float ai[4] = {a.x, a.y, a.z, a.w};
            float bj[4] = {b.x, b.y, b.z, b.w};
#pragma unroll
            for (int i = 0; i < 4; i++)
#pragma unroll
                for (int j = 0; j < 4; j++)
                    acc[i][j] += ai[i] * bj[j];
        }
        __syncthreads();
    }

    float4 bv = *(const float4*)(bias + n0 + (tx << 2));
    float bb[4] = {bv.x, bv.y, bv.z, bv.w};
#pragma unroll
    for (int i = 0; i < 4; i++) {
        int r = m0 + (ty << 2) + i;
        if (r < M) {
            float4 ov = make_float4(acc[i][0] + bb[0], acc[i][1] + bb[1],
                                    acc[i][2] + bb[2], acc[i][3] + bb[3]);
            *(float4*)(C + (size_t)r * N + n0 + (tx << 2)) = ov;
        }
    }
}

// ---------------------------------------------------------------------------
// Fused RMSNorm (over full dim) + RoPE (interleaved pairs, f/h/w freq split).
// In-place on y. One block per row.
// ---------------------------------------------------------------------------
__global__ __launch_bounds__(256) void rms_rope(
    float* __restrict__ y, const float* __restrict__ g,
    const float* __restrict__ freqs, const int* __restrict__ grid_sizes,
    int L, int dim, int c, int c0, int c1)
{
    const int l = blockIdx.x;
    float* row = y + (size_t)l * dim;

    // sum of squares
    float s = 0.f;
    for (int i = threadIdx.x; i < dim; i += blockDim.x) {
        float v = row[i];
        s += v * v;
    }
#pragma unroll
    for (int off = 16; off; off >>= 1)
        s += __shfl_down_sync(0xffffffffu, s, off);

    __shared__ float red[9];
    int warp = threadIdx.x >> 5, lane = threadIdx.x & 31;
    if (lane == 0) red[warp] = s;
    __syncthreads();
    if (threadIdx.x == 0) {
        float t = 0.f;
        for (int i = 0; i < 8; i++) t += red[i];
        red[8] = t;
    }
    __syncthreads();
    const float rs = rsqrtf(red[8] / (float)dim + 1e-6f);

    const int gf = grid_sizes[0], gh = grid_sizes[1], gw = grid_sizes[2];
    const int sl = gf * gh * gw;
    const bool rot = (l < sl);
    int fi = 0, hi = 0, wi = 0;
    if (rot) {
        fi = l / (gh * gw);
        int rem = l - fi * gh * gw;
        hi = rem / gw;
        wi = rem - hi * gw;
    }

    const int half = dim >> 1;
    for (int p = threadIdx.x; p < half; p += blockDim.x) {
        int head = p / c;
        int j = p - head * c;
        int i0 = head * 2 * c + 2 * j;
        float a = row[i0] * rs * g[i0];
        float b = row[i0 + 1] * rs * g[i0 + 1];
        if (rot) {
            int pos = (j < c0) ? fi : ((j < c0 + c1) ? hi : wi);
            float ang = freqs[pos * c + j];
            float sn, cs;
            sincosf(ang, &sn, &cs);
            row[i0]     = a * cs - b * sn;
            row[i0 + 1] = a * sn + b * cs;
        } else {
            row[i0] = a;
            row[i0 + 1] = b;
        }
    }
}

// ---------------------------------------------------------------------------
// Flash attention (fp32, online softmax).
// Per block: one head, 64 query rows. Key tiles of 64, d=128.
// Smem layouts are XOR-swizzled on 16B chunks: chunk' = chunk ^ ((row>>2)&7).
// ---------------------------------------------------------------------------
__device__ __forceinline__ void load_tile_sw(
    const float* __restrict__ src, float* __restrict__ dst,
    int row0, int L, size_t rowstride, int hoff, int tid)
{
#pragma unroll
    for (int it = 0; it < 8; it++) {
        int idx = tid + it * 256;         // 0..2047 chunk index
        int r = idx >> 5;                 // tile row 0..63
        int ch = idx & 31;                // 16B chunk within row
        float4 val = make_float4(0.f, 0.f, 0.f, 0.f);
        int gr = row0 + r;
        if (gr < L)
            val = *(const float4*)(src + (size_t)gr * rowstride + hoff + (ch << 2));
        int sch = ch ^ ((r >> 2) & 7);
        *(float4*)(dst + r * 128 + (sch << 2)) = val;
    }
}

__global__ __launch_bounds__(256) void flash_attn(
    const float* __restrict__ qg, const float* __restrict__ kg,
    const float* __restrict__ vg, float* __restrict__ og,
    int L, int nh, const int* __restrict__ seq_lens, float scale)
{
    extern __shared__ __align__(16) float sm[];
    float* Qs = sm;                 // 64*128 (swizzled)
    float* Ks = sm + 64 * 128;      // 64*128 (swizzled; reused for V)
    float* Ps = sm + 2 * 64 * 128;  // 64*65  (P transposed: [key][qrow])

    const int tid = threadIdx.x;
    const int tx = tid & 15;
    const int ty = tid >> 4;
    const int hh = blockIdx.y;
    const int q0 = blockIdx.x << 6;
    const int hoff = hh * 128;
    const size_t rowstride = (size_t)nh * 128;
    const int seqlen = seq_lens[0];

    load_tile_sw(qg, Qs, q0, L, rowstride, hoff, tid);

    float m_i[4], l_i[4], O[4][8];
#pragma unroll
    for (int i = 0; i < 4; i++) {
        m_i[i] = -1e30f;
        l_i[i] = 0.f;
#pragma unroll
        for (int j = 0; j < 8; j++) O[i][j] = 0.f;
    }

    const int r0 = ty << 2;
    const int c0 = tx << 2;
    const int schq = ty & 7;
    const int schk = tx & 7;
    const int nkt = (seqlen + 63) >> 6;

    __syncthreads();

    for (int kt = 0; kt < nkt; kt++) {
        const int kbase = kt << 6;

        load_tile_sw(kg, Ks, kbase, L, rowstride, hoff, tid);
        __syncthreads();

        // --- S = Q K^T (4x4 micro over 32 float4 chunks of d) ---
        float S[4][4];
#pragma unroll
        for (int i = 0; i < 4; i++)
#pragma unroll
            for (int j = 0; j < 4; j++) S[i][j] = 0.f;

#pragma unroll 8
        for (int ch = 0; ch < 32; ch++) {
            float4 qv[4], kv[4];
            int oq = (ch ^ schq) << 2;
            int ok = (ch ^ schk) << 2;
#pragma unroll
            for (int i = 0; i < 4; i++)
                qv[i] = *(const float4*)(Qs + (r0 + i) * 128 + oq);
#pragma unroll
            for (int j = 0; j < 4; j++)
                kv[j] = *(const float4*)(Ks + (c0 + j) * 128 + ok);
#pragma unroll
            for (int i = 0; i < 4; i++)
#pragma unroll
                for (int j = 0; j < 4; j++)
                    S[i][j] += qv[i].x * kv[j].x + qv[i].y * kv[j].y +
                               qv[i].z * kv[j].z + qv[i].w * kv[j].w;
        }

        // --- scale + key mask ---
#pragma unroll
        for (int i = 0; i < 4; i++)
#pragma unroll
            for (int j = 0; j < 4; j++) {
                float sv = S[i][j] * scale;
                if (kbase + c0 + j >= seqlen) sv = -1e30f;
                S[i][j] = sv;
            }

        // --- online softmax update (row reduce over 16 tx lanes) ---
#pragma unroll
        for (int i = 0; i < 4; i++) {
            float mx = fmaxf(fmaxf(S[i][0], S[i][1]), fmaxf(S[i][2], S[i][3]));
#pragma unroll
            for (int off = 8; off; off >>= 1)
                mx = fmaxf(mx, __shfl_xor_sync(0xffffffffu, mx, off));
            float mnew = fmaxf(m_i[i], mx);
            float cf = __expf(m_i[i] - mnew);
            float ssum = 0.f;
#pragma unroll
            for (int j = 0; j < 4; j++) {
                float p = __expf(S[i][j] - mnew);
                S[i][j] = p;
                ssum += p;
            }
#pragma unroll
            for (int off = 8; off; off >>= 1)
                ssum += __shfl_xor_sync(0xffffffffu, ssum, off);
            l_i[i] = l_i[i] * cf + ssum;
            m_i[i] = mnew;
#pragma unroll
            for (int jj = 0; jj < 8; jj++) O[i][jj] *= cf;
        }

        // --- store P transposed for PV ---
#pragma unroll
        for (int j = 0; j < 4; j++)
#pragma unroll
            for (int i = 0; i < 4; i++)
                Ps[(c0 + j) * 65 + r0 + i] = S[i][j];
        __syncthreads();

        // --- V tile overwrites Ks buffer ---
        load_tile_sw(vg, Ks, kbase, L, rowstride, hoff, tid);
        __syncthreads();

        // --- O += P V (thread covers rows r0..r0+3, cols 8tx..8tx+7) ---
        const int chO = tx << 1;  // base chunk of this thread's O columns
#pragma unroll 8
        for (int kk = 0; kk < 64; kk++) {
            float pi[4];
#pragma unroll
            for (int i = 0; i < 4; i++) pi[i] = Ps[kk * 65 + r0 + i];
            int sw = (kk >> 2) & 7;
            float4 va = *(const float4*)(Ks + kk * 128 + ((chO ^ sw) << 2));
            float4 vb = *(const float4*)(Ks + kk * 128 + (((chO + 1) ^ sw) << 2));
#pragma unroll
            for (int i = 0; i < 4; i++) {
                O[i][0] += pi[i] * va.x;
                O[i][1] += pi[i] * va.y;
                O[i][2] += pi[i] * va.z;
                O[i][3] += pi[i] * va.w;
                O[i][4] += pi[i] * vb.x;
                O[i][5] += pi[i] * vb.y;
                O[i][6] += pi[i] * vb.z;
                O[i][7] += pi[i] * vb.w;
            }
        }
        __syncthreads();   // before next K load reuses Ks
    }

    // --- normalize & store ---
#pragma unroll
    for (int i = 0; i < 4; i++) {
        int gr = q0 + r0 + i;
        if (gr >= L) continue;
        float inv = 1.0f / l_i[i];
        float4 o0 = make_float4(O[i][0] * inv, O[i][1] * inv,
                                O[i][2] * inv, O[i][3] * inv);
        float4 o1 = make_float4(O[i][4] * inv, O[i][5] * inv,
                                O[i][6] * inv, O[i][7] * inv);
        float* dst = og + (size_t)gr * rowstride + hoff + (tx << 3);
        *(float4*)dst = o0;
        *(float4*)(dst + 4) = o1;
    }
}

// ---------------------------------------------------------------------------
// kernel_launch
// Input order: x, seq_lens, grid_sizes, freqs, Wq, bq, Wk, bk, Wv, bv,
//              Wo, bo, gq, gk
// ---------------------------------------------------------------------------
extern "C" void kernel_launch(void* const* d_in, const int* in_sizes, int n_in,
                              void* d_out, int out_size)
{
    (void)n_in; (void)out_size;
    const float* x          = (const float*)d_in[0];
    const int*   seq_lens   = (const int*)d_in[1];
    const int*   grid_sizes = (const int*)d_in[2];
    const float* freqs      = (const float*)d_in[3];
    const float* Wq = (const float*)d_in[4];
    const float* bq = (const float*)d_in[5];
    const float* Wk = (const float*)d_in[6];
    const float* bk = (const float*)d_in[7];
    const float* Wv = (const float*)d_in[8];
    const float* bv = (const float*)d_in[9];
    const float* Wo = (const float*)d_in[10];
    const float* bo = (const float*)d_in[11];
    const float* gq = (const float*)d_in[12];
    const float* gk = (const float*)d_in[13];
    float* out = (float*)d_out;

    const int dim = in_sizes[5];             // 1536
    const int L   = in_sizes[0] / dim;       // 5000
    const int c   = in_sizes[3] / 1024;      // 64
    const int d   = 2 * c;                   // 128
    const int nh  = dim / d;                 // 12
    const int c1  = c / 3;                   // 21
    const int c0  = c - 2 * c1;              // 22

    float *qp, *kp, *vp, *op;
    cudaGetSymbolAddress((void**)&qp, g_q);
    cudaGetSymbolAddress((void**)&kp, g_k);
    cudaGetSymbolAddress((void**)&vp, g_v);
    cudaGetSymbolAddress((void**)&op, g_o);

    dim3 gblk(dim / 64, (L + 63) / 64);
    dim3 tblk(256);

    sgemm_bias<<<gblk, tblk>>>(x, Wq, bq, qp, L, dim, dim);
    sgemm_bias<<<gblk, tblk>>>(x, Wk, bk, kp, L, dim, dim);
    sgemm_bias<<<gblk, tblk>>>(x, Wv, bv, vp, L, dim, dim);

    rms_rope<<<L, 256>>>(qp, gq, freqs, grid_sizes, L, dim, c, c0, c1);
    rms_rope<<<L, 256>>>(kp, gk, freqs, grid_sizes, L, dim, c, c0, c1);

    const int smem_bytes = (2 * 64 * 128 + 64 * 65) * sizeof(float);  // 82176
    cudaFuncSetAttribute(flash_attn, cudaFuncAttributeMaxDynamicSharedMemorySize,
                         smem_bytes);
    dim3 fgrid((L + 63) / 64, nh);
    flash_attn<<<fgrid, 256, smem_bytes>>>(qp, kp, vp, op, L, nh, seq_lens,
                                           rsqrtf((float)d));

    sgemm_bias<<<gblk, tblk>>>(op, Wo, bo, out, L, dim, dim);
}

// round 4
// speedup vs baseline: 2.9074x; 2.9074x over previous
#include <cuda_runtime.h>
#include <cuda_bf16.h>
#include <math.h>
#include <stdint.h>

// ---------------------------------------------------------------------------
// Scratch buffers (device globals; no allocation allowed)
// ---------------------------------------------------------------------------
#define MAX_L   5000
#define DIMM    1536
__device__ float g_q[MAX_L * DIMM];
__device__ float g_k[MAX_L * DIMM];
__device__ float g_v[MAX_L * DIMM];
__device__ float g_o[MAX_L * DIMM];

// ---------------------------------------------------------------------------
// Helpers: tf32 convert, ldmatrix, mma
// ---------------------------------------------------------------------------
__device__ __forceinline__ uint32_t f2tf32(float f) {
    uint32_t r;
    asm("cvt.rna.tf32.f32 %0, %1;" : "=r"(r) : "f"(f));
    return r;
}

__device__ __forceinline__ void ldsm4(uint32_t* r, const float* p) {
    uint32_t a = (uint32_t)__cvta_generic_to_shared(p);
    asm volatile("ldmatrix.sync.aligned.m8n8.x4.shared.b16 {%0,%1,%2,%3}, [%4];"
                 : "=r"(r[0]), "=r"(r[1]), "=r"(r[2]), "=r"(r[3]) : "r"(a));
}

__device__ __forceinline__ void mma_tf32(float* d, const uint32_t* a,
                                         const uint32_t* b) {
    asm volatile(
        "mma.sync.aligned.m16n8k8.row.col.f32.tf32.tf32.f32 "
        "{%0,%1,%2,%3}, {%4,%5,%6,%7}, {%8,%9}, {%0,%1,%2,%3};"
        : "+f"(d[0]), "+f"(d[1]), "+f"(d[2]), "+f"(d[3])
        : "r"(a[0]), "r"(a[1]), "r"(a[2]), "r"(a[3]), "r"(b[0]), "r"(b[1]));
}

// ---------------------------------------------------------------------------
// tf32 tensor-core GEMM: C[M,N] = A[M,K] @ W[K,N] + bias
// 128x128x32 block tile, 8 warps (2x4), warp tile 64x32.
// ---------------------------------------------------------------------------
#define GLDA 36   // smem row stride (words) for As[m][k] and Bs[n][k]

__global__ __launch_bounds__(256, 2) void gemm_tf32(
    const float* __restrict__ A, const float* __restrict__ W,
    const float* __restrict__ bias, float* __restrict__ C,
    int M, int N, int K)
{
    __shared__ __align__(16) float As[128 * GLDA];
    __shared__ __align__(16) float Bs[128 * GLDA];

    const int tid = threadIdx.x;
    const int wid = tid >> 5;
    const int lane = tid & 31;
    const int wm = wid >> 2;          // 0..1
    const int wn = wid & 3;           // 0..3
    const int m0 = blockIdx.y << 7;
    const int n0 = blockIdx.x << 7;

    // ldmatrix lane address components
    const int lrA = (lane & 7) + ((lane >> 3) & 1) * 8;  // A row within 16-tile
    const int lcA = (lane >> 4) * 4;                     // A k-word offset
    const int lrB = (lane & 7) + ((lane >> 4) << 3);     // B n-row within pair
    const int lcB = ((lane >> 3) & 1) * 4;               // B k-word offset

    float acc[4][4][4];
#pragma unroll
    for (int mt = 0; mt < 4; mt++)
#pragma unroll
        for (int nt = 0; nt < 4; nt++)
#pragma unroll
            for (int i = 0; i < 4; i++) acc[mt][nt][i] = 0.f;

    for (int k0 = 0; k0 < K; k0 += 32) {
        // --- load A tile (rows m, k contiguous float4) ---
#pragma unroll
        for (int it = 0; it < 4; it++) {
            int idx = tid + it * 256;
            int row = idx >> 3;
            int c4 = (idx & 7) << 2;
            float4 v = make_float4(0.f, 0.f, 0.f, 0.f);
            int gr = m0 + row;
            if (gr < M) v = *(const float4*)(A + (size_t)gr * K + k0 + c4);
            uint4 t;
            t.x = f2tf32(v.x); t.y = f2tf32(v.y);
            t.z = f2tf32(v.z); t.w = f2tf32(v.w);
            *(uint4*)&As[row * GLDA + c4] = t;
        }
        // --- load B tile transposed: Bs[n][k] ---
#pragma unroll
        for (int it = 0; it < 4; it++) {
            int idx = tid + it * 256;
            int n = idx & 127;
            int k4 = (idx >> 7) << 2;
            const float* wp = W + (size_t)(k0 + k4) * N + n0 + n;
            uint4 t;
            t.x = f2tf32(wp[0]);
            t.y = f2tf32(wp[N]);
            t.z = f2tf32(wp[2 * N]);
            t.w = f2tf32(wp[3 * N]);
            *(uint4*)&Bs[n * GLDA + k4] = t;
        }
        __syncthreads();

#pragma unroll
        for (int ks = 0; ks < 4; ks++) {
            uint32_t af[4][4], bf[2][4];
#pragma unroll
            for (int mt = 0; mt < 4; mt++)
                ldsm4(af[mt], &As[(wm * 64 + mt * 16 + lrA) * GLDA + ks * 8 + lcA]);
#pragma unroll
            for (int np = 0; np < 2; np++)
                ldsm4(bf[np], &Bs[(wn * 32 + np * 16 + lrB) * GLDA + ks * 8 + lcB]);
#pragma unroll
            for (int mt = 0; mt < 4; mt++)
#pragma unroll
                for (int nt = 0; nt < 4; nt++)
                    mma_tf32(acc[mt][nt], af[mt], &bf[nt >> 1][(nt & 1) * 2]);
        }
        __syncthreads();
    }

    // --- epilogue ---
    const int q = lane & 3;
    const int rb = lane >> 2;
#pragma unroll
    for (int nt = 0; nt < 4; nt++) {
        int col = n0 + wn * 32 + nt * 8 + q * 2;
        float2 bv = *(const float2*)(bias + col);
#pragma unroll
        for (int mt = 0; mt < 4; mt++) {
            int r = m0 + wm * 64 + mt * 16 + rb;
            if (r < M) {
                float2 o = make_float2(acc[mt][nt][0] + bv.x, acc[mt][nt][1] + bv.y);
                *(float2*)(C + (size_t)r * N + col) = o;
            }
            if (r + 8 < M) {
                float2 o = make_float2(acc[mt][nt][2] + bv.x, acc[mt][nt][3] + bv.y);
                *(float2*)(C + (size_t)(r + 8) * N + col) = o;
            }
        }
    }
}

// ---------------------------------------------------------------------------
// Fused RMSNorm + RoPE (unchanged from round 2)
// ---------------------------------------------------------------------------
__global__ __launch_bounds__(256) void rms_rope(
    float* __restrict__ y, const float* __restrict__ g,
    const float* __restrict__ freqs, const int* __restrict__ grid_sizes,
    int L, int dim, int c, int c0, int c1)
{
    const int l = blockIdx.x;
    float* row = y + (size_t)l * dim;

    float s = 0.f;
    for (int i = threadIdx.x; i < dim; i += blockDim.x) {
        float v = row[i];
        s += v * v;
    }
#pragma unroll
    for (int off = 16; off; off >>= 1)
        s += __shfl_down_sync(0xffffffffu, s, off);

    __shared__ float red[9];
    int warp = threadIdx.x >> 5, lane = threadIdx.x & 31;
    if (lane == 0) red[warp] = s;
    __syncthreads();
    if (threadIdx.x == 0) {
        float t = 0.f;
        for (int i = 0; i < 8; i++) t += red[i];
        red[8] = t;
    }
    __syncthreads();
    const float rs = rsqrtf(red[8] / (float)dim + 1e-6f);

    const int gf = grid_sizes[0], gh = grid_sizes[1], gw = grid_sizes[2];
    const int sl = gf * gh * gw;
    const bool rot = (l < sl);
    int fi = 0, hi = 0, wi = 0;
    if (rot) {
        fi = l / (gh * gw);
        int rem = l - fi * gh * gw;
        hi = rem / gw;
        wi = rem - hi * gw;
    }

    const int half = dim >> 1;
    for (int p = threadIdx.x; p < half; p += blockDim.x) {
        int head = p / c;
        int j = p - head * c;
        int i0 = head * 2 * c + 2 * j;
        float a = row[i0] * rs * g[i0];
        float b = row[i0 + 1] * rs * g[i0 + 1];
        if (rot) {
            int pos = (j < c0) ? fi : ((j < c0 + c1) ? hi : wi);
            float ang = freqs[pos * c + j];
            float sn, cs;
            sincosf(ang, &sn, &cs);
            row[i0]     = a * cs - b * sn;
            row[i0 + 1] = a * sn + b * cs;
        } else {
            row[i0] = a;
            row[i0 + 1] = b;
        }
    }
}

// ---------------------------------------------------------------------------
// tf32 tensor-core flash attention.
// Block = 64 q rows x 1 head. 4 warps, each warp owns 16 q rows.
// Q fragment register-resident; online softmax + P-fragment shuffle in regs.
// Smem: Ks[64][132] (K tile, also Q staging), Vt[128][68] (V transposed).
// ---------------------------------------------------------------------------
#define KLD 132   // Ks row stride (words)
#define VLD 68    // Vt row stride (words)

__global__ __launch_bounds__(128) void attn_tf32(
    const float* __restrict__ qg, const float* __restrict__ kg,
    const float* __restrict__ vg, float* __restrict__ og,
    int L, int nh, const int* __restrict__ seq_lens)
{
    extern __shared__ __align__(16) float sm[];
    float* Ks = sm;                 // 64*132
    float* Vt = sm + 64 * KLD;      // 128*68

    const int tid = threadIdx.x;
    const int wid = tid >> 5;
    const int lane = tid & 31;
    const int q = lane & 3;
    const int rb = lane >> 2;
    const int head = blockIdx.y;
    const int q0 = blockIdx.x << 6;
    const int hoff = head * 128;
    const size_t stride = (size_t)nh * 128;
    const int seqlen = seq_lens[0];
    const float scale = rsqrtf(128.0f);

    // ldmatrix lane components
    const int lrA = (lane & 7) + ((lane >> 3) & 1) * 8;
    const int lcA = (lane >> 4) * 4;
    const int lrB = (lane & 7) + ((lane >> 4) << 3);
    const int lcB = ((lane >> 3) & 1) * 4;

    // ---- stage Q into Ks, build register Q fragment ----
#pragma unroll
    for (int it = 0; it < 16; it++) {
        int idx = tid + it * 128;
        int row = idx >> 5;
        int c4 = (idx & 31) << 2;
        float4 v = make_float4(0.f, 0.f, 0.f, 0.f);
        int gr = q0 + row;
        if (gr < L) v = *(const float4*)(qg + (size_t)gr * stride + hoff + c4);
        uint4 t;
        t.x = f2tf32(v.x * scale); t.y = f2tf32(v.y * scale);
        t.z = f2tf32(v.z * scale); t.w = f2tf32(v.w * scale);
        *(uint4*)&Ks[row * KLD + c4] = t;
    }
    __syncthreads();

    uint32_t qf[16][4];
#pragma unroll
    for (int ks = 0; ks < 16; ks++)
        ldsm4(qf[ks], &Ks[(wid * 16 + lrA) * KLD + ks * 8 + lcA]);
    __syncthreads();

    float o[16][4];
#pragma unroll
    for (int nt = 0; nt < 16; nt++)
#pragma unroll
        for (int i = 0; i < 4; i++) o[nt][i] = 0.f;
    float m_r[2] = {-1e30f, -1e30f};
    float l_r[2] = {0.f, 0.f};

    const int nkt = (seqlen + 63) >> 6;
    const int key_lo = lane & 7;
    const int d4_lo = lane >> 3;     // 0..3

    for (int t64 = 0; t64 < nkt; t64++) {
        const int kbase = t64 << 6;

        // ---- load K tile into Ks ----
#pragma unroll
        for (int it = 0; it < 16; it++) {
            int idx = tid + it * 128;
            int row = idx >> 5;
            int c4 = (idx & 31) << 2;
            float4 v = make_float4(0.f, 0.f, 0.f, 0.f);
            int gr = kbase + row;
            if (gr < L) v = *(const float4*)(kg + (size_t)gr * stride + hoff + c4);
            uint4 t;
            t.x = f2tf32(v.x); t.y = f2tf32(v.y);
            t.z = f2tf32(v.z); t.w = f2tf32(v.w);
            *(uint4*)&Ks[row * KLD + c4] = t;
        }

        // ---- load V tile transposed into Vt[d][key] ----
#pragma unroll
        for (int kh = 0; kh < 2; kh++) {
#pragma unroll
            for (int dh = 0; dh < 8; dh++) {
                int key = (2 * wid + kh) * 8 + key_lo;
                int d4 = dh * 4 + d4_lo;
                int gr = kbase + key;
                float4 v = make_float4(0.f, 0.f, 0.f, 0.f);
                if (gr < L)
                    v = *(const float4*)(vg + (size_t)gr * stride + hoff + d4 * 4);
                Vt[(d4 * 4 + 0) * VLD + key] = __uint_as_float(f2tf32(v.x));
                Vt[(d4 * 4 + 1) * VLD + key] = __uint_as_float(f2tf32(v.y));
                Vt[(d4 * 4 + 2) * VLD + key] = __uint_as_float(f2tf32(v.z));
                Vt[(d4 * 4 + 3) * VLD + key] = __uint_as_float(f2tf32(v.w));
            }
        }
        __syncthreads();

        // ---- S = Q K^T ----
        float s[8][4];
#pragma unroll
        for (int nt = 0; nt < 8; nt++)
#pragma unroll
            for (int i = 0; i < 4; i++) s[nt][i] = 0.f;

#pragma unroll
        for (int ks = 0; ks < 16; ks++) {
#pragma unroll
            for (int np = 0; np < 4; np++) {
                uint32_t bf[4];
                ldsm4(bf, &Ks[(np * 16 + lrB) * KLD + ks * 8 + lcB]);
                mma_tf32(s[2 * np], qf[ks], bf);
                mma_tf32(s[2 * np + 1], qf[ks], bf + 2);
            }
        }

        // ---- mask ----
#pragma unroll
        for (int nt = 0; nt < 8; nt++) {
            int col = kbase + nt * 8 + 2 * q;
            if (col >= seqlen)     { s[nt][0] = -1e30f; s[nt][2] = -1e30f; }
            if (col + 1 >= seqlen) { s[nt][1] = -1e30f; s[nt][3] = -1e30f; }
        }

        // ---- online softmax (per fragment row) ----
#pragma unroll
        for (int r = 0; r < 2; r++) {
            float mx = -1e30f;
#pragma unroll
            for (int nt = 0; nt < 8; nt++)
                mx = fmaxf(mx, fmaxf(s[nt][2 * r], s[nt][2 * r + 1]));
            mx = fmaxf(mx, __shfl_xor_sync(0xffffffffu, mx, 1));
            mx = fmaxf(mx, __shfl_xor_sync(0xffffffffu, mx, 2));
            float mn = fmaxf(m_r[r], mx);
            float cf = __expf(m_r[r] - mn);
            m_r[r] = mn;
            float sum = 0.f;
#pragma unroll
            for (int nt = 0; nt < 8; nt++) {
                float p0 = __expf(s[nt][2 * r] - mn);
                float p1 = __expf(s[nt][2 * r + 1] - mn);
                s[nt][2 * r] = p0;
                s[nt][2 * r + 1] = p1;
                sum += p0 + p1;
            }
            sum += __shfl_xor_sync(0xffffffffu, sum, 1);
            sum += __shfl_xor_sync(0xffffffffu, sum, 2);
            l_r[r] = l_r[r] * cf + sum;
#pragma unroll
            for (int nt = 0; nt < 16; nt++) {
                o[nt][2 * r] *= cf;
                o[nt][2 * r + 1] *= cf;
            }
        }

        // ---- O += P V ----
        const int srcA = (lane & ~3) | (q >> 1);
        const int srcB = srcA + 2;
        const bool oddk = (q & 1);
#pragma unroll
        for (int kt = 0; kt < 8; kt++) {
            float u0 = __shfl_sync(0xffffffffu, s[kt][0], srcA);
            float u1 = __shfl_sync(0xffffffffu, s[kt][1], srcA);
            float u2 = __shfl_sync(0xffffffffu, s[kt][2], srcA);
            float u3 = __shfl_sync(0xffffffffu, s[kt][3], srcA);
            float w0 = __shfl_sync(0xffffffffu, s[kt][0], srcB);
            float w1 = __shfl_sync(0xffffffffu, s[kt][1], srcB);
            float w2 = __shfl_sync(0xffffffffu, s[kt][2], srcB);
            float w3 = __shfl_sync(0xffffffffu, s[kt][3], srcB);
            uint32_t aP[4];
            aP[0] = f2tf32(oddk ? u1 : u0);
            aP[1] = f2tf32(oddk ? u3 : u2);
            aP[2] = f2tf32(oddk ? w1 : w0);
            aP[3] = f2tf32(oddk ? w3 : w2);
#pragma unroll
            for (int np = 0; np < 8; np++) {
                uint32_t bf[4];
                ldsm4(bf, &Vt[(np * 16 + lrB) * VLD + kt * 8 + lcB]);
                mma_tf32(o[2 * np], aP, bf);
                mma_tf32(o[2 * np + 1], aP, bf + 2);
            }
        }
        __syncthreads();
    }

    // ---- normalize + store ----
    float inv0 = 1.0f / l_r[0];
    float inv1 = 1.0f / l_r[1];
    int r = q0 + wid * 16 + rb;
#pragma unroll
    for (int nt = 0; nt < 16; nt++) {
        int col = hoff + nt * 8 + 2 * q;
        if (r < L) {
            float2 v = make_float2(o[nt][0] * inv0, o[nt][1] * inv0);
            *(float2*)(og + (size_t)r * stride + col) = v;
        }
        if (r + 8 < L) {
            float2 v = make_float2(o[nt][2] * inv1, o[nt][3] * inv1);
            *(float2*)(og + (size_t)(r + 8) * stride + col) = v;
        }
    }
}

// ---------------------------------------------------------------------------
// kernel_launch
// ---------------------------------------------------------------------------
extern "C" void kernel_launch(void* const* d_in, const int* in_sizes, int n_in,
                              void* d_out, int out_size)
{
    (void)n_in; (void)out_size;
    const float* x          = (const float*)d_in[0];
    const int*   seq_lens   = (const int*)d_in[1];
    const int*   grid_sizes = (const int*)d_in[2];
    const float* freqs      = (const float*)d_in[3];
    const float* Wq = (const float*)d_in[4];
    const float* bq = (const float*)d_in[5];
    const float* Wk = (const float*)d_in[6];
    const float* bk = (const float*)d_in[7];
    const float* Wv = (const float*)d_in[8];
    const float* bv = (const float*)d_in[9];
    const float* Wo = (const float*)d_in[10];
    const float* bo = (const float*)d_in[11];
    const float* gq = (const float*)d_in[12];
    const float* gk = (const float*)d_in[13];
    float* out = (float*)d_out;

    const int dim = in_sizes[5];             // 1536
    const int L   = in_sizes[0] / dim;       // 5000
    const int c   = in_sizes[3] / 1024;      // 64
    const int d   = 2 * c;                   // 128
    const int nh  = dim / d;                 // 12
    const int c1  = c / 3;                   // 21
    const int c0  = c - 2 * c1;              // 22

    float *qp, *kp, *vp, *op;
    cudaGetSymbolAddress((void**)&qp, g_q);
    cudaGetSymbolAddress((void**)&kp, g_k);
    cudaGetSymbolAddress((void**)&vp, g_v);
    cudaGetSymbolAddress((void**)&op, g_o);

    dim3 gblk(dim / 128, (L + 127) / 128);
    dim3 tblk(256);

    gemm_tf32<<<gblk, tblk>>>(x, Wq, bq, qp, L, dim, dim);
    gemm_tf32<<<gblk, tblk>>>(x, Wk, bk, kp, L, dim, dim);
    gemm_tf32<<<gblk, tblk>>>(x, Wv, bv, vp, L, dim, dim);

    rms_rope<<<L, 256>>>(qp, gq, freqs, grid_sizes, L, dim, c, c0, c1);
    rms_rope<<<L, 256>>>(kp, gk, freqs, grid_sizes, L, dim, c, c0, c1);

    const int smem_bytes = (64 * KLD + 128 * VLD) * sizeof(float);  // 68608
    cudaFuncSetAttribute(attn_tf32, cudaFuncAttributeMaxDynamicSharedMemorySize,
                         smem_bytes);
    dim3 fgrid((L + 63) / 64, nh);
    attn_tf32<<<fgrid, 128, smem_bytes>>>(qp, kp, vp, op, L, nh, seq_lens);

    gemm_tf32<<<gblk, tblk>>>(op, Wo, bo, out, L, dim, dim);
}

// round 9
// speedup vs baseline: 3.7655x; 1.2952x over previous
#include <cuda_runtime.h>
#include <cuda_fp16.h>
#include <math.h>
#include <stdint.h>

// ---------------------------------------------------------------------------
// Scratch buffers (device globals; no allocation allowed)
// ---------------------------------------------------------------------------
#define MAX_L   5000
#define DIMM    1536
__device__ float g_q[MAX_L * DIMM];
__device__ float g_k[MAX_L * DIMM];
__device__ float g_v[MAX_L * DIMM];
__device__ float g_o[MAX_L * DIMM];

// ---------------------------------------------------------------------------
// Helpers
// ---------------------------------------------------------------------------
__device__ __forceinline__ uint32_t packh2(float a, float b) {
    __half2 h = __floats2half2_rn(a, b);
    return *(uint32_t*)&h;
}

__device__ __forceinline__ uint4 pack8(float4 x, float4 y) {
    uint4 r;
    r.x = packh2(x.x, x.y);
    r.y = packh2(x.z, x.w);
    r.z = packh2(y.x, y.y);
    r.w = packh2(y.z, y.w);
    return r;
}

__device__ __forceinline__ void ldsm4h(uint32_t* r, const __half* p) {
    uint32_t a = (uint32_t)__cvta_generic_to_shared(p);
    asm volatile("ldmatrix.sync.aligned.m8n8.x4.shared.b16 {%0,%1,%2,%3}, [%4];"
                 : "=r"(r[0]), "=r"(r[1]), "=r"(r[2]), "=r"(r[3]) : "r"(a));
}

__device__ __forceinline__ void mma_f16(float* d, const uint32_t* a,
                                        const uint32_t* b) {
    asm volatile(
        "mma.sync.aligned.m16n8k16.row.col.f32.f16.f16.f32 "
        "{%0,%1,%2,%3}, {%4,%5,%6,%7}, {%8,%9}, {%0,%1,%2,%3};"
        : "+f"(d[0]), "+f"(d[1]), "+f"(d[2]), "+f"(d[3])
        : "r"(a[0]), "r"(a[1]), "r"(a[2]), "r"(a[3]), "r"(b[0]), "r"(b[1]));
}

// ---------------------------------------------------------------------------
// fp16 tensor-core GEMM: C[M,N] = A[M,K] @ W[K,N] + bias
// 128x128x32 block tile, 8 warps (2x4), warp tile 64x32, m16n8k16.
// Register prefetch of the next k-slab (converted to half2) overlaps loads
// with the mma block.
// ---------------------------------------------------------------------------
#define GLDH 40   // smem row stride in halves (80B, 16B-aligned)

__global__ __launch_bounds__(256, 2) void gemm_f16(
    const float* __restrict__ A, const float* __restrict__ W,
    const float* __restrict__ bias, float* __restrict__ C,
    int M, int N, int K)
{
    __shared__ __align__(16) __half As[128 * GLDH];
    __shared__ __align__(16) __half Bs[128 * GLDH];

    const int tid = threadIdx.x;
    const int wid = tid >> 5;
    const int lane = tid & 31;
    const int wm = wid >> 2;
    const int wn = wid & 3;
    const int m0 = blockIdx.y << 7;
    const int n0 = blockIdx.x << 7;

    // ldmatrix lane geometry (half units)
    const int lrA = (lane & 7) + ((lane >> 3) & 1) * 8;
    const int lcA = (lane >> 4) * 8;
    const int lrB = (lane & 7) + ((lane >> 4) << 3);
    const int lcB = ((lane >> 3) & 1) * 8;

    // load geometry
    const int ar = tid >> 1;               // A row 0..127
    const int hc = (tid & 1) << 4;         // A half-chunk 0 / 16
    const int bn = tid & 127;              // B n-row
    const int bkh = (tid >> 7) << 4;       // B k-half 0 / 16
    const int gr = m0 + ar;

    float acc[4][4][4];
#pragma unroll
    for (int mt = 0; mt < 4; mt++)
#pragma unroll
        for (int nt = 0; nt < 4; nt++)
#pragma unroll
            for (int i = 0; i < 4; i++) acc[mt][nt][i] = 0.f;

    const int NS = K >> 5;
    uint4 pa0, pa1, pb0, pb1;

    // prefetch slab 0
    {
        float4 z = make_float4(0.f, 0.f, 0.f, 0.f);
        float4 f0 = z, f1 = z, f2 = z, f3 = z;
        if (gr < M) {
            const float4* p = (const float4*)(A + (size_t)gr * K + hc);
            f0 = p[0]; f1 = p[1]; f2 = p[2]; f3 = p[3];
        }
        pa0 = pack8(f0, f1); pa1 = pack8(f2, f3);
        const float* wp = W + (size_t)bkh * N + n0 + bn;
        uint32_t u[8];
#pragma unroll
        for (int c = 0; c < 8; c++)
            u[c] = packh2(wp[(size_t)(2 * c) * N], wp[(size_t)(2 * c + 1) * N]);
        pb0 = make_uint4(u[0], u[1], u[2], u[3]);
        pb1 = make_uint4(u[4], u[5], u[6], u[7]);
    }

    for (int s = 0; s < NS; s++) {
        __syncthreads();
        *(uint4*)&As[ar * GLDH + hc] = pa0;
        *(uint4*)&As[ar * GLDH + hc + 8] = pa1;
        *(uint4*)&Bs[bn * GLDH + bkh] = pb0;
        *(uint4*)&Bs[bn * GLDH + bkh + 8] = pb1;
        __syncthreads();

        if (s + 1 < NS) {
            const int k0 = (s + 1) << 5;
            float4 z = make_float4(0.f, 0.f, 0.f, 0.f);
            float4 f0 = z, f1 = z, f2 = z, f3 = z;
            if (gr < M) {
                const float4* p = (const float4*)(A + (size_t)gr * K + k0 + hc);
                f0 = p[0]; f1 = p[1]; f2 = p[2]; f3 = p[3];
            }
            pa0 = pack8(f0, f1); pa1 = pack8(f2, f3);
            const float* wp = W + (size_t)(k0 + bkh) * N + n0 + bn;
            uint32_t u[8];
#pragma unroll
            for (int c = 0; c < 8; c++)
                u[c] = packh2(wp[(size_t)(2 * c) * N],
                              wp[(size_t)(2 * c + 1) * N]);
            pb0 = make_uint4(u[0], u[1], u[2], u[3]);
            pb1 = make_uint4(u[4], u[5], u[6], u[7]);
        }

#pragma unroll
        for (int ks = 0; ks < 2; ks++) {
            uint32_t af[4][4], bf[2][4];
#pragma unroll
            for (int mt = 0; mt < 4; mt++)
                ldsm4h(af[mt], &As[(wm * 64 + mt * 16 + lrA) * GLDH + ks * 16 + lcA]);
#pragma unroll
            for (int np = 0; np < 2; np++)
                ldsm4h(bf[np], &Bs[(wn * 32 + np * 16 + lrB) * GLDH + ks * 16 + lcB]);
#pragma unroll
            for (int mt = 0; mt < 4; mt++)
#pragma unroll
                for (int nt = 0; nt < 4; nt++)
                    mma_f16(acc[mt][nt], af[mt], &bf[nt >> 1][(nt & 1) * 2]);
        }
    }

    // epilogue
    const int q = lane & 3;
    const int rb = lane >> 2;
#pragma unroll
    for (int nt = 0; nt < 4; nt++) {
        int col = n0 + wn * 32 + nt * 8 + q * 2;
        float2 bv = *(const float2*)(bias + col);
#pragma unroll
        for (int mt = 0; mt < 4; mt++) {
            int r = m0 + wm * 64 + mt * 16 + rb;
            if (r < M) {
                float2 o = make_float2(acc[mt][nt][0] + bv.x, acc[mt][nt][1] + bv.y);
                *(float2*)(C + (size_t)r * N + col) = o;
            }
            if (r + 8 < M) {
                float2 o = make_float2(acc[mt][nt][2] + bv.x, acc[mt][nt][3] + bv.y);
                *(float2*)(C + (size_t)(r + 8) * N + col) = o;
            }
        }
    }
}

// ---------------------------------------------------------------------------
// Fused RMSNorm + RoPE (unchanged)
// ---------------------------------------------------------------------------
__global__ __launch_bounds__(256) void rms_rope(
    float* __restrict__ y, const float* __restrict__ g,
    const float* __restrict__ freqs, const int* __restrict__ grid_sizes,
    int L, int dim, int c, int c0, int c1)
{
    const int l = blockIdx.x;
    float* row = y + (size_t)l * dim;

    float s = 0.f;
    for (int i = threadIdx.x; i < dim; i += blockDim.x) {
        float v = row[i];
        s += v * v;
    }
#pragma unroll
    for (int off = 16; off; off >>= 1)
        s += __shfl_down_sync(0xffffffffu, s, off);

    __shared__ float red[9];
    int warp = threadIdx.x >> 5, lane = threadIdx.x & 31;
    if (lane == 0) red[warp] = s;
    __syncthreads();
    if (threadIdx.x == 0) {
        float t = 0.f;
        for (int i = 0; i < 8; i++) t += red[i];
        red[8] = t;
    }
    __syncthreads();
    const float rs = rsqrtf(red[8] / (float)dim + 1e-6f);

    const int gf = grid_sizes[0], gh = grid_sizes[1], gw = grid_sizes[2];
    const int sl = gf * gh * gw;
    const bool rot = (l < sl);
    int fi = 0, hi = 0, wi = 0;
    if (rot) {
        fi = l / (gh * gw);
        int rem = l - fi * gh * gw;
        hi = rem / gw;
        wi = rem - hi * gw;
    }

    const int half = dim >> 1;
    for (int p = threadIdx.x; p < half; p += blockDim.x) {
        int head = p / c;
        int j = p - head * c;
        int i0 = head * 2 * c + 2 * j;
        float a = row[i0] * rs * g[i0];
        float b = row[i0 + 1] * rs * g[i0 + 1];
        if (rot) {
            int pos = (j < c0) ? fi : ((j < c0 + c1) ? hi : wi);
            float ang = freqs[pos * c + j];
            float sn, cs;
            sincosf(ang, &sn, &cs);
            row[i0]     = a * cs - b * sn;
            row[i0 + 1] = a * sn + b * cs;
        } else {
            row[i0] = a;
            row[i0 + 1] = b;
        }
    }
}

// ---------------------------------------------------------------------------
// fp16 tensor-core flash attention (m16n8k16).
// Block = 64 q rows x 1 head, 4 warps (16 q rows each).
// Q fragment register-resident; P->A fragment conversion is lane-identity
// (no shuffles). Smem: Ks[64][136] halves, Vt[128][72] halves.
// ---------------------------------------------------------------------------
#define KLD2 136
#define VLD2 72

__global__ __launch_bounds__(128) void attn_f16(
    const float* __restrict__ qg, const float* __restrict__ kg,
    const float* __restrict__ vg, float* __restrict__ og,
    int L, int nh, const int* __restrict__ seq_lens)
{
    extern __shared__ __align__(16) __half smh[];
    __half* Ks = smh;                 // 64*136
    __half* Vt = smh + 64 * KLD2;     // 128*72

    const int tid = threadIdx.x;
    const int wid = tid >> 5;
    const int lane = tid & 31;
    const int q = lane & 3;
    const int rb = lane >> 2;
    const int head = blockIdx.y;
    const int q0 = blockIdx.x << 6;
    const int hoff = head * 128;
    const size_t stride = (size_t)nh * 128;
    const int seqlen = seq_lens[0];
    const float scale = rsqrtf(128.0f);

    const int lrA = (lane & 7) + ((lane >> 3) & 1) * 8;
    const int lcA = (lane >> 4) * 8;
    const int lrB = (lane & 7) + ((lane >> 4) << 3);
    const int lcB = ((lane >> 3) & 1) * 8;

    // ---- stage Q (scaled, fp16) into Ks, build register Q fragment ----
#pragma unroll
    for (int it = 0; it < 16; it++) {
        int idx = tid + it * 128;
        int row = idx >> 5;
        int c4 = (idx & 31) << 2;
        float4 v = make_float4(0.f, 0.f, 0.f, 0.f);
        int grr = q0 + row;
        if (grr < L) v = *(const float4*)(qg + (size_t)grr * stride + hoff + c4);
        uint2 t;
        t.x = packh2(v.x * scale, v.y * scale);
        t.y = packh2(v.z * scale, v.w * scale);
        *(uint2*)&Ks[row * KLD2 + c4] = t;
    }
    __syncthreads();

    uint32_t qf[8][4];
#pragma unroll
    for (int ks = 0; ks < 8; ks++)
        ldsm4h(qf[ks], &Ks[(wid * 16 + lrA) * KLD2 + ks * 16 + lcA]);
    __syncthreads();

    float o[16][4];
#pragma unroll
    for (int nt = 0; nt < 16; nt++)
#pragma unroll
        for (int i = 0; i < 4; i++) o[nt][i] = 0.f;
    float m_r[2] = {-1e30f, -1e30f};
    float l_r[2] = {0.f, 0.f};

    const int nkt = (seqlen + 63) >> 6;
    const int key_lo = lane & 7;
    const int d4_lo = lane >> 3;

    for (int t64 = 0; t64 < nkt; t64++) {
        const int kbase = t64 << 6;

        // ---- K tile -> Ks (fp16) ----
#pragma unroll
        for (int it = 0; it < 16; it++) {
            int idx = tid + it * 128;
            int row = idx >> 5;
            int c4 = (idx & 31) << 2;
            float4 v = make_float4(0.f, 0.f, 0.f, 0.f);
            int grr = kbase + row;
            if (grr < L) v = *(const float4*)(kg + (size_t)grr * stride + hoff + c4);
            uint2 t;
            t.x = packh2(v.x, v.y);
            t.y = packh2(v.z, v.w);
            *(uint2*)&Ks[row * KLD2 + c4] = t;
        }

        // ---- V tile transposed -> Vt[d][key] (fp16) ----
#pragma unroll
        for (int kh = 0; kh < 2; kh++) {
#pragma unroll
            for (int dh = 0; dh < 8; dh++) {
                int key = (2 * wid + kh) * 8 + key_lo;
                int d4 = dh * 4 + d4_lo;
                int grr = kbase + key;
                float4 v = make_float4(0.f, 0.f, 0.f, 0.f);
                if (grr < L)
                    v = *(const float4*)(vg + (size_t)grr * stride + hoff + d4 * 4);
                Vt[(d4 * 4 + 0) * VLD2 + key] = __float2half_rn(v.x);
                Vt[(d4 * 4 + 1) * VLD2 + key] = __float2half_rn(v.y);
                Vt[(d4 * 4 + 2) * VLD2 + key] = __float2half_rn(v.z);
                Vt[(d4 * 4 + 3) * VLD2 + key] = __float2half_rn(v.w);
            }
        }
        __syncthreads();

        // ---- S = Q K^T ----
        float s[8][4];
#pragma unroll
        for (int nt = 0; nt < 8; nt++)
#pragma unroll
            for (int i = 0; i < 4; i++) s[nt][i] = 0.f;

#pragma unroll
        for (int ks = 0; ks < 8; ks++) {
#pragma unroll
            for (int np = 0; np < 4; np++) {
                uint32_t bf[4];
                ldsm4h(bf, &Ks[(np * 16 + lrB) * KLD2 + ks * 16 + lcB]);
                mma_f16(s[2 * np], qf[ks], bf);
                mma_f16(s[2 * np + 1], qf[ks], bf + 2);
            }
        }

        // ---- mask ----
#pragma unroll
        for (int nt = 0; nt < 8; nt++) {
            int col = kbase + nt * 8 + 2 * q;
            if (col >= seqlen)     { s[nt][0] = -1e30f; s[nt][2] = -1e30f; }
            if (col + 1 >= seqlen) { s[nt][1] = -1e30f; s[nt][3] = -1e30f; }
        }

        // ---- online softmax ----
#pragma unroll
        for (int r = 0; r < 2; r++) {
            float mx = -1e30f;
#pragma unroll
            for (int nt = 0; nt < 8; nt++)
                mx = fmaxf(mx, fmaxf(s[nt][2 * r], s[nt][2 * r + 1]));
            mx = fmaxf(mx, __shfl_xor_sync(0xffffffffu, mx, 1));
            mx = fmaxf(mx, __shfl_xor_sync(0xffffffffu, mx, 2));
            float mn = fmaxf(m_r[r], mx);
            float cf = __expf(m_r[r] - mn);
            m_r[r] = mn;
            float sum = 0.f;
#pragma unroll
            for (int nt = 0; nt < 8; nt++) {
                float p0 = __expf(s[nt][2 * r] - mn);
                float p1 = __expf(s[nt][2 * r + 1] - mn);
                s[nt][2 * r] = p0;
                s[nt][2 * r + 1] = p1;
                sum += p0 + p1;
            }
            sum += __shfl_xor_sync(0xffffffffu, sum, 1);
            sum += __shfl_xor_sync(0xffffffffu, sum, 2);
            l_r[r] = l_r[r] * cf + sum;
#pragma unroll
            for (int nt = 0; nt < 16; nt++) {
                o[nt][2 * r] *= cf;
                o[nt][2 * r + 1] *= cf;
            }
        }

        // ---- O += P V (P->A fragment is lane-identity for fp16 k16) ----
#pragma unroll
        for (int kt = 0; kt < 4; kt++) {
            uint32_t aP[4];
            aP[0] = packh2(s[2 * kt][0], s[2 * kt][1]);
            aP[1] = packh2(s[2 * kt][2], s[2 * kt][3]);
            aP[2] = packh2(s[2 * kt + 1][0], s[2 * kt + 1][1]);
            aP[3] = packh2(s[2 * kt + 1][2], s[2 * kt + 1][3]);
#pragma unroll
            for (int np = 0; np < 8; np++) {
                uint32_t bf[4];
                ldsm4h(bf, &Vt[(np * 16 + lrB) * VLD2 + kt * 16 + lcB]);
                mma_f16(o[2 * np], aP, bf);
                mma_f16(o[2 * np + 1], aP, bf + 2);
            }
        }
        __syncthreads();
    }

    // ---- normalize + store ----
    float inv0 = 1.0f / l_r[0];
    float inv1 = 1.0f / l_r[1];
    int r = q0 + wid * 16 + rb;
#pragma unroll
    for (int nt = 0; nt < 16; nt++) {
        int col = hoff + nt * 8 + 2 * q;
        if (r < L) {
            float2 v = make_float2(o[nt][0] * inv0, o[nt][1] * inv0);
            *(float2*)(og + (size_t)r * stride + col) = v;
        }
        if (r + 8 < L) {
            float2 v = make_float2(o[nt][2] * inv1, o[nt][3] * inv1);
            *(float2*)(og + (size_t)(r + 8) * stride + col) = v;
        }
    }
}

// ---------------------------------------------------------------------------
// kernel_launch
// ---------------------------------------------------------------------------
extern "C" void kernel_launch(void* const* d_in, const int* in_sizes, int n_in,
                              void* d_out, int out_size)
{
    (void)n_in; (void)out_size;
    const float* x          = (const float*)d_in[0];
    const int*   seq_lens   = (const int*)d_in[1];
    const int*   grid_sizes = (const int*)d_in[2];
    const float* freqs      = (const float*)d_in[3];
    const float* Wq = (const float*)d_in[4];
    const float* bq = (const float*)d_in[5];
    const float* Wk = (const float*)d_in[6];
    const float* bk = (const float*)d_in[7];
    const float* Wv = (const float*)d_in[8];
    const float* bv = (const float*)d_in[9];
    const float* Wo = (const float*)d_in[10];
    const float* bo = (const float*)d_in[11];
    const float* gq = (const float*)d_in[12];
    const float* gk = (const float*)d_in[13];
    float* out = (float*)d_out;

    const int dim = in_sizes[5];             // 1536
    const int L   = in_sizes[0] / dim;       // 5000
    const int c   = in_sizes[3] / 1024;      // 64
    const int d   = 2 * c;                   // 128
    const int nh  = dim / d;                 // 12
    const int c1  = c / 3;                   // 21
    const int c0  = c - 2 * c1;              // 22

    float *qp, *kp, *vp, *op;
    cudaGetSymbolAddress((void**)&qp, g_q);
    cudaGetSymbolAddress((void**)&kp, g_k);
    cudaGetSymbolAddress((void**)&vp, g_v);
    cudaGetSymbolAddress((void**)&op, g_o);

    dim3 gblk(dim / 128, (L + 127) / 128);
    dim3 tblk(256);

    gemm_f16<<<gblk, tblk>>>(x, Wq, bq, qp, L, dim, dim);
    gemm_f16<<<gblk, tblk>>>(x, Wk, bk, kp, L, dim, dim);
    gemm_f16<<<gblk, tblk>>>(x, Wv, bv, vp, L, dim, dim);

    rms_rope<<<L, 256>>>(qp, gq, freqs, grid_sizes, L, dim, c, c0, c1);
    rms_rope<<<L, 256>>>(kp, gk, freqs, grid_sizes, L, dim, c, c0, c1);

    const int attn_smem = (64 * KLD2 + 128 * VLD2) * (int)sizeof(__half); // 35840
    cudaFuncSetAttribute(attn_f16, cudaFuncAttributeMaxDynamicSharedMemorySize,
                         attn_smem);
    dim3 fgrid((L + 63) / 64, nh);
    attn_f16<<<fgrid, 128, attn_smem>>>(qp, kp, vp, op, L, nh, seq_lens);

    gemm_f16<<<gblk, tblk>>>(op, Wo, bo, out, L, dim, dim);
}

// round 10
// speedup vs baseline: 5.6294x; 1.4950x over previous
#include <cuda_runtime.h>
#include <cuda_fp16.h>
#include <math.h>
#include <stdint.h>

// ---------------------------------------------------------------------------
// Scratch buffers (device globals; no allocation allowed)
// ---------------------------------------------------------------------------
#define MAX_L   5000
#define DIMM    1536
__device__ float  g_q[MAX_L * DIMM];
__device__ float  g_k[MAX_L * DIMM];
__device__ float  g_v[MAX_L * DIMM];
__device__ __half g_qh[MAX_L * DIMM];
__device__ __half g_kh[MAX_L * DIMM];
__device__ __half g_vh[MAX_L * DIMM];
__device__ __half g_oh[MAX_L * DIMM];

// ---------------------------------------------------------------------------
// Helpers
// ---------------------------------------------------------------------------
__device__ __forceinline__ uint32_t packh2(float a, float b) {
    __half2 h = __floats2half2_rn(a, b);
    return *(uint32_t*)&h;
}

__device__ __forceinline__ uint4 pack8(float4 x, float4 y) {
    uint4 r;
    r.x = packh2(x.x, x.y);
    r.y = packh2(x.z, x.w);
    r.z = packh2(y.x, y.y);
    r.w = packh2(y.z, y.w);
    return r;
}

__device__ __forceinline__ void ldsm4h(uint32_t* r, const __half* p) {
    uint32_t a = (uint32_t)__cvta_generic_to_shared(p);
    asm volatile("ldmatrix.sync.aligned.m8n8.x4.shared.b16 {%0,%1,%2,%3}, [%4];"
                 : "=r"(r[0]), "=r"(r[1]), "=r"(r[2]), "=r"(r[3]) : "r"(a));
}

__device__ __forceinline__ void ldsm4t(uint32_t* r, const __half* p) {
    uint32_t a = (uint32_t)__cvta_generic_to_shared(p);
    asm volatile(
        "ldmatrix.sync.aligned.m8n8.x4.trans.shared.b16 {%0,%1,%2,%3}, [%4];"
        : "=r"(r[0]), "=r"(r[1]), "=r"(r[2]), "=r"(r[3]) : "r"(a));
}

__device__ __forceinline__ void mma_f16(float* d, const uint32_t* a,
                                        const uint32_t* b) {
    asm volatile(
        "mma.sync.aligned.m16n8k16.row.col.f32.f16.f16.f32 "
        "{%0,%1,%2,%3}, {%4,%5,%6,%7}, {%8,%9}, {%0,%1,%2,%3};"
        : "+f"(d[0]), "+f"(d[1]), "+f"(d[2]), "+f"(d[3])
        : "r"(a[0]), "r"(a[1]), "r"(a[2]), "r"(a[3]), "r"(b[0]), "r"(b[1]));
}

__device__ __forceinline__ void cpa16(uint32_t dst, const void* src, int sz) {
    asm volatile("cp.async.cg.shared.global [%0], [%1], 16, %2;"
                 :: "r"(dst), "l"(src), "r"(sz) : "memory");
}
__device__ __forceinline__ void cpa_commit() {
    asm volatile("cp.async.commit_group;" ::: "memory");
}

// ---------------------------------------------------------------------------
// fp16 tensor-core GEMM (templated on A dtype):
// C[M,N] = A[M,K] @ W[K,N] + bias ; 128x128x32 tile, 8 warps, m16n8k16,
// register prefetch of next k-slab.
// ---------------------------------------------------------------------------
#define GLDH 40

template<bool AH>
__global__ __launch_bounds__(256, 2) void gemm_f16_t(
    const void* __restrict__ Av, const float* __restrict__ W,
    const float* __restrict__ bias, float* __restrict__ C,
    int M, int N, int K)
{
    __shared__ __align__(16) __half As[128 * GLDH];
    __shared__ __align__(16) __half Bs[128 * GLDH];

    const float* Af = (const float*)Av;
    const __half* Ahp = (const __half*)Av;

    const int tid = threadIdx.x;
    const int wid = tid >> 5;
    const int lane = tid & 31;
    const int wm = wid >> 2;
    const int wn = wid & 3;
    const int m0 = blockIdx.y << 7;
    const int n0 = blockIdx.x << 7;

    const int lrA = (lane & 7) + ((lane >> 3) & 1) * 8;
    const int lcA = (lane >> 4) * 8;
    const int lrB = (lane & 7) + ((lane >> 4) << 3);
    const int lcB = ((lane >> 3) & 1) * 8;

    const int ar = tid >> 1;
    const int hc = (tid & 1) << 4;         // element offset within k-slab
    const int bn = tid & 127;
    const int bkh = (tid >> 7) << 4;
    const int gr = m0 + ar;

    float acc[4][4][4];
#pragma unroll
    for (int mt = 0; mt < 4; mt++)
#pragma unroll
        for (int nt = 0; nt < 4; nt++)
#pragma unroll
            for (int i = 0; i < 4; i++) acc[mt][nt][i] = 0.f;

    const int NS = K >> 5;
    uint4 pa0, pa1, pb0, pb1;

    auto fetchA = [&](int k0) {
        if (AH) {
            uint4 z = make_uint4(0u, 0u, 0u, 0u);
            pa0 = z; pa1 = z;
            if (gr < M) {
                const uint4* p = (const uint4*)(Ahp + (size_t)gr * K + k0 + hc);
                pa0 = p[0]; pa1 = p[1];
            }
        } else {
            float4 z = make_float4(0.f, 0.f, 0.f, 0.f);
            float4 f0 = z, f1 = z, f2 = z, f3 = z;
            if (gr < M) {
                const float4* p = (const float4*)(Af + (size_t)gr * K + k0 + hc);
                f0 = p[0]; f1 = p[1]; f2 = p[2]; f3 = p[3];
            }
            pa0 = pack8(f0, f1); pa1 = pack8(f2, f3);
        }
    };
    auto fetchB = [&](int k0) {
        const float* wp = W + (size_t)(k0 + bkh) * N + n0 + bn;
        uint32_t u[8];
#pragma unroll
        for (int c = 0; c < 8; c++)
            u[c] = packh2(wp[(size_t)(2 * c) * N], wp[(size_t)(2 * c + 1) * N]);
        pb0 = make_uint4(u[0], u[1], u[2], u[3]);
        pb1 = make_uint4(u[4], u[5], u[6], u[7]);
    };

    fetchA(0); fetchB(0);

    for (int s = 0; s < NS; s++) {
        __syncthreads();
        *(uint4*)&As[ar * GLDH + hc] = pa0;
        *(uint4*)&As[ar * GLDH + hc + 8] = pa1;
        *(uint4*)&Bs[bn * GLDH + bkh] = pb0;
        *(uint4*)&Bs[bn * GLDH + bkh + 8] = pb1;
        __syncthreads();

        if (s + 1 < NS) { fetchA((s + 1) << 5); fetchB((s + 1) << 5); }

#pragma unroll
        for (int ks = 0; ks < 2; ks++) {
            uint32_t af[4][4], bf[2][4];
#pragma unroll
            for (int mt = 0; mt < 4; mt++)
                ldsm4h(af[mt], &As[(wm * 64 + mt * 16 + lrA) * GLDH + ks * 16 + lcA]);
#pragma unroll
            for (int np = 0; np < 2; np++)
                ldsm4h(bf[np], &Bs[(wn * 32 + np * 16 + lrB) * GLDH + ks * 16 + lcB]);
#pragma unroll
            for (int mt = 0; mt < 4; mt++)
#pragma unroll
                for (int nt = 0; nt < 4; nt++)
                    mma_f16(acc[mt][nt], af[mt], &bf[nt >> 1][(nt & 1) * 2]);
        }
    }

    const int q = lane & 3;
    const int rb = lane >> 2;
#pragma unroll
    for (int nt = 0; nt < 4; nt++) {
        int col = n0 + wn * 32 + nt * 8 + q * 2;
        float2 bv = *(const float2*)(bias + col);
#pragma unroll
        for (int mt = 0; mt < 4; mt++) {
            int r = m0 + wm * 64 + mt * 16 + rb;
            if (r < M) {
                float2 o = make_float2(acc[mt][nt][0] + bv.x, acc[mt][nt][1] + bv.y);
                *(float2*)(C + (size_t)r * N + col) = o;
            }
            if (r + 8 < M) {
                float2 o = make_float2(acc[mt][nt][2] + bv.x, acc[mt][nt][3] + bv.y);
                *(float2*)(C + (size_t)(r + 8) * N + col) = o;
            }
        }
    }
}

// ---------------------------------------------------------------------------
// Fused RMSNorm + RoPE; reads fp32, writes fp16.
// ---------------------------------------------------------------------------
__global__ __launch_bounds__(256) void rms_rope(
    const float* __restrict__ y, __half* __restrict__ yh,
    const float* __restrict__ g,
    const float* __restrict__ freqs, const int* __restrict__ grid_sizes,
    int L, int dim, int c, int c0, int c1)
{
    const int l = blockIdx.x;
    const float* row = y + (size_t)l * dim;
    __half* rowh = yh + (size_t)l * dim;

    float s = 0.f;
    for (int i = threadIdx.x; i < dim; i += blockDim.x) {
        float v = row[i];
        s += v * v;
    }
#pragma unroll
    for (int off = 16; off; off >>= 1)
        s += __shfl_down_sync(0xffffffffu, s, off);

    __shared__ float red[9];
    int warp = threadIdx.x >> 5, lane = threadIdx.x & 31;
    if (lane == 0) red[warp] = s;
    __syncthreads();
    if (threadIdx.x == 0) {
        float t = 0.f;
        for (int i = 0; i < 8; i++) t += red[i];
        red[8] = t;
    }
    __syncthreads();
    const float rs = rsqrtf(red[8] / (float)dim + 1e-6f);

    const int gf = grid_sizes[0], gh = grid_sizes[1], gw = grid_sizes[2];
    const int sl = gf * gh * gw;
    const bool rot = (l < sl);
    int fi = 0, hi = 0, wi = 0;
    if (rot) {
        fi = l / (gh * gw);
        int rem = l - fi * gh * gw;
        hi = rem / gw;
        wi = rem - hi * gw;
    }

    const int half = dim >> 1;
    for (int p = threadIdx.x; p < half; p += blockDim.x) {
        int head = p / c;
        int j = p - head * c;
        int i0 = head * 2 * c + 2 * j;
        float a = row[i0] * rs * g[i0];
        float b = row[i0 + 1] * rs * g[i0 + 1];
        float o0 = a, o1 = b;
        if (rot) {
            int pos = (j < c0) ? fi : ((j < c0 + c1) ? hi : wi);
            float ang = freqs[pos * c + j];
            float sn, cs;
            sincosf(ang, &sn, &cs);
            o0 = a * cs - b * sn;
            o1 = a * sn + b * cs;
        }
        *(__half2*)(rowh + i0) = __floats2half2_rn(o0, o1);
    }
}

// ---------------------------------------------------------------------------
// fp32 -> fp16 convert (for V)
// ---------------------------------------------------------------------------
__global__ __launch_bounds__(256) void f2h(const float* __restrict__ src,
                                           __half* __restrict__ dst, int n)
{
    int i = (blockIdx.x * 256 + threadIdx.x) * 4;
    if (i < n) {
        float4 v = *(const float4*)(src + i);
        uint2 t;
        t.x = packh2(v.x, v.y);
        t.y = packh2(v.z, v.w);
        *(uint2*)(dst + i) = t;
    }
}

// ---------------------------------------------------------------------------
// fp16 flash attention: half inputs, cp.async double-buffered K/V tiles,
// ldmatrix.trans for V (no transpose store). 64 q rows x 1 head per CTA,
// 4 warps. Scale folded into post-S step. Output written as fp16.
// ---------------------------------------------------------------------------
#define LDK 136   // smem row stride (halves) for 128-half rows
#define TBYTES (64 * LDK * 2)

__global__ __launch_bounds__(128) void attn_f16(
    const __half* __restrict__ qg, const __half* __restrict__ kg,
    const __half* __restrict__ vg, __half* __restrict__ og,
    int L, int nh, const int* __restrict__ seq_lens)
{
    extern __shared__ __align__(16) __half smh[];
    __half* ksp[2] = { smh,            smh + 64 * LDK };
    __half* vsp[2] = { smh + 2 * 64 * LDK, smh + 3 * 64 * LDK };

    const int tid = threadIdx.x;
    const int wid = tid >> 5;
    const int lane = tid & 31;
    const int q = lane & 3;
    const int rb = lane >> 2;
    const int head = blockIdx.y;
    const int q0 = blockIdx.x << 6;
    const int hoff = head * 128;
    const size_t stride = (size_t)nh * 128;
    const int seqlen = seq_lens[0];
    const float scale = rsqrtf(128.0f);

    const int lrA = (lane & 7) + ((lane >> 3) & 1) * 8;
    const int lcA = (lane >> 4) * 8;
    const int lrB = (lane & 7) + ((lane >> 4) << 3);
    const int lcB = ((lane >> 3) & 1) * 8;
    // trans-ldmatrix (V) lane geometry
    const int trow = lane & 15;
    const int tcol = (lane >> 4) << 3;

    const uint32_t ksb[2] = { (uint32_t)__cvta_generic_to_shared(ksp[0]),
                              (uint32_t)__cvta_generic_to_shared(ksp[1]) };
    const uint32_t vsb[2] = { (uint32_t)__cvta_generic_to_shared(vsp[0]),
                              (uint32_t)__cvta_generic_to_shared(vsp[1]) };

    const int nkt = (seqlen + 63) >> 6;

    auto stage_kv = [&](int t) {
        const int buf = t & 1;
        const int kbase = t << 6;
#pragma unroll
        for (int it = 0; it < 8; it++) {
            int idx = tid + it * 128;
            int row = idx >> 4;
            int ch = idx & 15;
            int gr = kbase + row;
            int sz = (gr < L) ? 16 : 0;
            size_t goff = (size_t)gr * stride + hoff + ch * 8;
            uint32_t so = (uint32_t)(row * LDK + ch * 8) * 2;
            cpa16(ksb[buf] + so, kg + goff, sz);
            cpa16(vsb[buf] + so, vg + goff, sz);
        }
        cpa_commit();
    };

    // issue K/V tile 0, then stage Q into vsp[1]
    stage_kv(0);
#pragma unroll
    for (int it = 0; it < 8; it++) {
        int idx = tid + it * 128;
        int row = idx >> 4;
        int ch = idx & 15;
        int gr = q0 + row;
        int sz = (gr < L) ? 16 : 0;
        cpa16(vsb[1] + (uint32_t)(row * LDK + ch * 8) * 2,
              qg + (size_t)gr * stride + hoff + ch * 8, sz);
    }
    cpa_commit();
    asm volatile("cp.async.wait_group 0;" ::: "memory");
    __syncthreads();

    uint32_t qf[8][4];
#pragma unroll
    for (int ks = 0; ks < 8; ks++)
        ldsm4h(qf[ks], &vsp[1][(wid * 16 + lrA) * LDK + ks * 16 + lcA]);
    __syncthreads();

    float o[16][4];
#pragma unroll
    for (int nt = 0; nt < 16; nt++)
#pragma unroll
        for (int i = 0; i < 4; i++) o[nt][i] = 0.f;
    float m_r[2] = {-1e30f, -1e30f};
    float l_r[2] = {0.f, 0.f};

    for (int t = 0; t < nkt; t++) {
        const int buf = t & 1;
        const int kbase = t << 6;
        const __half* Ks = ksp[buf];
        const __half* Vs = vsp[buf];

        if (t + 1 < nkt) {
            stage_kv(t + 1);
            asm volatile("cp.async.wait_group 1;" ::: "memory");
        } else {
            asm volatile("cp.async.wait_group 0;" ::: "memory");
        }
        __syncthreads();

        // ---- S = Q K^T ----
        float s[8][4];
#pragma unroll
        for (int nt = 0; nt < 8; nt++)
#pragma unroll
            for (int i = 0; i < 4; i++) s[nt][i] = 0.f;

#pragma unroll
        for (int ks = 0; ks < 8; ks++) {
#pragma unroll
            for (int np = 0; np < 4; np++) {
                uint32_t bf[4];
                ldsm4h(bf, &Ks[(np * 16 + lrB) * LDK + ks * 16 + lcB]);
                mma_f16(s[2 * np], qf[ks], bf);
                mma_f16(s[2 * np + 1], qf[ks], bf + 2);
            }
        }

        // ---- scale + mask ----
#pragma unroll
        for (int nt = 0; nt < 8; nt++) {
            int col = kbase + nt * 8 + 2 * q;
            s[nt][0] = (col     < seqlen) ? s[nt][0] * scale : -1e30f;
            s[nt][2] = (col     < seqlen) ? s[nt][2] * scale : -1e30f;
            s[nt][1] = (col + 1 < seqlen) ? s[nt][1] * scale : -1e30f;
            s[nt][3] = (col + 1 < seqlen) ? s[nt][3] * scale : -1e30f;
        }

        // ---- online softmax ----
#pragma unroll
        for (int r = 0; r < 2; r++) {
            float mx = -1e30f;
#pragma unroll
            for (int nt = 0; nt < 8; nt++)
                mx = fmaxf(mx, fmaxf(s[nt][2 * r], s[nt][2 * r + 1]));
            mx = fmaxf(mx, __shfl_xor_sync(0xffffffffu, mx, 1));
            mx = fmaxf(mx, __shfl_xor_sync(0xffffffffu, mx, 2));
            float mn = fmaxf(m_r[r], mx);
            float cf = __expf(m_r[r] - mn);
            m_r[r] = mn;
            float sum = 0.f;
#pragma unroll
            for (int nt = 0; nt < 8; nt++) {
                float p0 = __expf(s[nt][2 * r] - mn);
                float p1 = __expf(s[nt][2 * r + 1] - mn);
                s[nt][2 * r] = p0;
                s[nt][2 * r + 1] = p1;
                sum += p0 + p1;
            }
            sum += __shfl_xor_sync(0xffffffffu, sum, 1);
            sum += __shfl_xor_sync(0xffffffffu, sum, 2);
            l_r[r] = l_r[r] * cf + sum;
#pragma unroll
            for (int nt = 0; nt < 16; nt++) {
                o[nt][2 * r] *= cf;
                o[nt][2 * r + 1] *= cf;
            }
        }

        // ---- O += P V  (V via ldmatrix.trans; P->A lane-identity) ----
#pragma unroll
        for (int kt = 0; kt < 4; kt++) {
            uint32_t aP[4];
            aP[0] = packh2(s[2 * kt][0], s[2 * kt][1]);
            aP[1] = packh2(s[2 * kt][2], s[2 * kt][3]);
            aP[2] = packh2(s[2 * kt + 1][0], s[2 * kt + 1][1]);
            aP[3] = packh2(s[2 * kt + 1][2], s[2 * kt + 1][3]);
            const __half* vrow = &Vs[(kt * 16 + trow) * LDK + tcol];
#pragma unroll
            for (int np = 0; np < 8; np++) {
                uint32_t bf[4];
                ldsm4t(bf, vrow + np * 16);
                mma_f16(o[2 * np], aP, bf);
                mma_f16(o[2 * np + 1], aP, bf + 2);
            }
        }
        __syncthreads();
    }

    // ---- normalize + store (fp16) ----
    float inv0 = 1.0f / l_r[0];
    float inv1 = 1.0f / l_r[1];
    int r = q0 + wid * 16 + rb;
#pragma unroll
    for (int nt = 0; nt < 16; nt++) {
        int col = hoff + nt * 8 + 2 * q;
        if (r < L)
            *(__half2*)(og + (size_t)r * stride + col) =
                __floats2half2_rn(o[nt][0] * inv0, o[nt][1] * inv0);
        if (r + 8 < L)
            *(__half2*)(og + (size_t)(r + 8) * stride + col) =
                __floats2half2_rn(o[nt][2] * inv1, o[nt][3] * inv1);
    }
}

// ---------------------------------------------------------------------------
// kernel_launch
// ---------------------------------------------------------------------------
extern "C" void kernel_launch(void* const* d_in, const int* in_sizes, int n_in,
                              void* d_out, int out_size)
{
    (void)n_in; (void)out_size;
    const float* x          = (const float*)d_in[0];
    const int*   seq_lens   = (const int*)d_in[1];
    const int*   grid_sizes = (const int*)d_in[2];
    const float* freqs      = (const float*)d_in[3];
    const float* Wq = (const float*)d_in[4];
    const float* bq = (const float*)d_in[5];
    const float* Wk = (const float*)d_in[6];
    const float* bk = (const float*)d_in[7];
    const float* Wv = (const float*)d_in[8];
    const float* bv = (const float*)d_in[9];
    const float* Wo = (const float*)d_in[10];
    const float* bo = (const float*)d_in[11];
    const float* gq = (const float*)d_in[12];
    const float* gk = (const float*)d_in[13];
    float* out = (float*)d_out;

    const int dim = in_sizes[5];             // 1536
    const int L   = in_sizes[0] / dim;       // 5000
    const int c   = in_sizes[3] / 1024;      // 64
    const int d   = 2 * c;                   // 128
    const int nh  = dim / d;                 // 12
    const int c1  = c / 3;                   // 21
    const int c0  = c - 2 * c1;              // 22

    float *qp, *kp, *vp;
    __half *qh, *kh, *vh, *oh;
    cudaGetSymbolAddress((void**)&qp, g_q);
    cudaGetSymbolAddress((void**)&kp, g_k);
    cudaGetSymbolAddress((void**)&vp, g_v);
    cudaGetSymbolAddress((void**)&qh, g_qh);
    cudaGetSymbolAddress((void**)&kh, g_kh);
    cudaGetSymbolAddress((void**)&vh, g_vh);
    cudaGetSymbolAddress((void**)&oh, g_oh);

    dim3 gblk(dim / 128, (L + 127) / 128);
    dim3 tblk(256);

    gemm_f16_t<false><<<gblk, tblk>>>(x, Wq, bq, qp, L, dim, dim);
    gemm_f16_t<false><<<gblk, tblk>>>(x, Wk, bk, kp, L, dim, dim);
    gemm_f16_t<false><<<gblk, tblk>>>(x, Wv, bv, vp, L, dim, dim);

    rms_rope<<<L, 256>>>(qp, qh, gq, freqs, grid_sizes, L, dim, c, c0, c1);
    rms_rope<<<L, 256>>>(kp, kh, gk, freqs, grid_sizes, L, dim, c, c0, c1);
    f2h<<<(L * dim) / 1024, 256>>>(vp, vh, L * dim);

    const int attn_smem = 4 * 64 * LDK * (int)sizeof(__half);  // 69632
    cudaFuncSetAttribute(attn_f16, cudaFuncAttributeMaxDynamicSharedMemorySize,
                         attn_smem);
    dim3 fgrid((L + 63) / 64, nh);
    attn_f16<<<fgrid, 128, attn_smem>>>(qh, kh, vh, oh, L, nh, seq_lens);

    gemm_f16_t<true><<<gblk, tblk>>>(oh, Wo, bo, out, L, dim, dim);
}

// round 11
// speedup vs baseline: 5.7254x; 1.0171x over previous
#include <cuda_runtime.h>
#include <cuda_fp16.h>
#include <math.h>
#include <stdint.h>

// ---------------------------------------------------------------------------
// Scratch buffers (device globals; no allocation allowed)
// ---------------------------------------------------------------------------
#define MAX_L   5000
#define DIMM    1536
__device__ float  g_q[MAX_L * DIMM];
__device__ float  g_k[MAX_L * DIMM];
__device__ float  g_v[MAX_L * DIMM];
__device__ __half g_xh[MAX_L * DIMM];
__device__ __half g_qh[MAX_L * DIMM];
__device__ __half g_kh[MAX_L * DIMM];
__device__ __half g_vh[MAX_L * DIMM];
__device__ __half g_oh[MAX_L * DIMM];
__device__ __half g_wq[DIMM * DIMM];
__device__ __half g_wk[DIMM * DIMM];
__device__ __half g_wv[DIMM * DIMM];
__device__ __half g_wo[DIMM * DIMM];

// ---------------------------------------------------------------------------
// Helpers
// ---------------------------------------------------------------------------
__device__ __forceinline__ uint32_t packh2(float a, float b) {
    __half2 h = __floats2half2_rn(a, b);
    return *(uint32_t*)&h;
}

__device__ __forceinline__ void ldsm4h(uint32_t* r, const __half* p) {
    uint32_t a = (uint32_t)__cvta_generic_to_shared(p);
    asm volatile("ldmatrix.sync.aligned.m8n8.x4.shared.b16 {%0,%1,%2,%3}, [%4];"
                 : "=r"(r[0]), "=r"(r[1]), "=r"(r[2]), "=r"(r[3]) : "r"(a));
}

__device__ __forceinline__ void ldsm4t(uint32_t* r, const __half* p) {
    uint32_t a = (uint32_t)__cvta_generic_to_shared(p);
    asm volatile(
        "ldmatrix.sync.aligned.m8n8.x4.trans.shared.b16 {%0,%1,%2,%3}, [%4];"
        : "=r"(r[0]), "=r"(r[1]), "=r"(r[2]), "=r"(r[3]) : "r"(a));
}

__device__ __forceinline__ void mma_f16(float* d, const uint32_t* a,
                                        const uint32_t* b) {
    asm volatile(
        "mma.sync.aligned.m16n8k16.row.col.f32.f16.f16.f32 "
        "{%0,%1,%2,%3}, {%4,%5,%6,%7}, {%8,%9}, {%0,%1,%2,%3};"
        : "+f"(d[0]), "+f"(d[1]), "+f"(d[2]), "+f"(d[3])
        : "r"(a[0]), "r"(a[1]), "r"(a[2]), "r"(a[3]), "r"(b[0]), "r"(b[1]));
}

__device__ __forceinline__ void cpa16(uint32_t dst, const void* src, int sz) {
    asm volatile("cp.async.cg.shared.global [%0], [%1], 16, %2;"
                 :: "r"(dst), "l"(src), "r"(sz) : "memory");
}
__device__ __forceinline__ void cpa_commit() {
    asm volatile("cp.async.commit_group;" ::: "memory");
}

// ---------------------------------------------------------------------------
// Prep: fp32 -> fp16 convert
// ---------------------------------------------------------------------------
__global__ __launch_bounds__(256) void f2h(const float* __restrict__ src,
                                           __half* __restrict__ dst, int n)
{
    int i = (blockIdx.x * 256 + threadIdx.x) * 4;
    if (i < n) {
        float4 v = *(const float4*)(src + i);
        uint2 t;
        t.x = packh2(v.x, v.y);
        t.y = packh2(v.z, v.w);
        *(uint2*)(dst + i) = t;
    }
}

// ---------------------------------------------------------------------------
// Prep: transpose + convert W[K][N] fp32 -> Wt[N][K] fp16 (K,N mult of 32)
// ---------------------------------------------------------------------------
__global__ __launch_bounds__(256) void transpose_h(
    const float* __restrict__ W, __half* __restrict__ Wt, int K, int N)
{
    __shared__ float t[32][33];
    const int tx = threadIdx.x & 31;
    const int ty = threadIdx.x >> 5;
    const int n0 = blockIdx.x << 5;
    const int k0 = blockIdx.y << 5;
#pragma unroll
    for (int i = 0; i < 4; i++)
        t[ty + 8 * i][tx] = W[(size_t)(k0 + ty + 8 * i) * N + n0 + tx];
    __syncthreads();
#pragma unroll
    for (int i = 0; i < 4; i++)
        Wt[(size_t)(n0 + ty + 8 * i) * K + k0 + tx] =
            __float2half_rn(t[tx][ty + 8 * i]);
}

// ---------------------------------------------------------------------------
// all-fp16 tensor-core GEMM: C[M,N] = A[M,K] @ Wt[N,K]^T + bias
// A half [M][K], Wt half [N][K] (pre-transposed). 128x128x32 tile, 8 warps,
// m16n8k16, register prefetch (2 uint4 per operand per slab).
// ---------------------------------------------------------------------------
#define GLDH 40

__global__ __launch_bounds__(256, 2) void gemm_hh(
    const __half* __restrict__ A, const __half* __restrict__ Wt,
    const float* __restrict__ bias, float* __restrict__ C,
    int M, int N, int K)
{
    __shared__ __align__(16) __half As[128 * GLDH];
    __shared__ __align__(16) __half Bs[128 * GLDH];

    const int tid = threadIdx.x;
    const int wid = tid >> 5;
    const int lane = tid & 31;
    const int wm = wid >> 2;
    const int wn = wid & 3;
    const int m0 = blockIdx.y << 7;
    const int n0 = blockIdx.x << 7;

    const int lrA = (lane & 7) + ((lane >> 3) & 1) * 8;
    const int lcA = (lane >> 4) * 8;
    const int lrB = (lane & 7) + ((lane >> 4) << 3);
    const int lcB = ((lane >> 3) & 1) * 8;

    const int ar = tid >> 1;
    const int hc = (tid & 1) << 4;
    const int bn = tid & 127;
    const int bkh = (tid >> 7) << 4;
    const int gr = m0 + ar;

    float acc[4][4][4];
#pragma unroll
    for (int mt = 0; mt < 4; mt++)
#pragma unroll
        for (int nt = 0; nt < 4; nt++)
#pragma unroll
            for (int i = 0; i < 4; i++) acc[mt][nt][i] = 0.f;

    const int NS = K >> 5;
    uint4 pa0, pa1, pb0, pb1;

    auto fetchA = [&](int k0) {
        uint4 z = make_uint4(0u, 0u, 0u, 0u);
        pa0 = z; pa1 = z;
        if (gr < M) {
            const uint4* p = (const uint4*)(A + (size_t)gr * K + k0 + hc);
            pa0 = p[0]; pa1 = p[1];
        }
    };
    auto fetchB = [&](int k0) {
        const uint4* p = (const uint4*)(Wt + (size_t)(n0 + bn) * K + k0 + bkh);
        pb0 = p[0]; pb1 = p[1];
    };

    fetchA(0); fetchB(0);

    for (int s = 0; s < NS; s++) {
        __syncthreads();
        *(uint4*)&As[ar * GLDH + hc] = pa0;
        *(uint4*)&As[ar * GLDH + hc + 8] = pa1;
        *(uint4*)&Bs[bn * GLDH + bkh] = pb0;
        *(uint4*)&Bs[bn * GLDH + bkh + 8] = pb1;
        __syncthreads();

        if (s + 1 < NS) { fetchA((s + 1) << 5); fetchB((s + 1) << 5); }

#pragma unroll
        for (int ks = 0; ks < 2; ks++) {
            uint32_t af[4][4], bf[2][4];
#pragma unroll
            for (int mt = 0; mt < 4; mt++)
                ldsm4h(af[mt], &As[(wm * 64 + mt * 16 + lrA) * GLDH + ks * 16 + lcA]);
#pragma unroll
            for (int np = 0; np < 2; np++)
                ldsm4h(bf[np], &Bs[(wn * 32 + np * 16 + lrB) * GLDH + ks * 16 + lcB]);
#pragma unroll
            for (int mt = 0; mt < 4; mt++)
#pragma unroll
                for (int nt = 0; nt < 4; nt++)
                    mma_f16(acc[mt][nt], af[mt], &bf[nt >> 1][(nt & 1) * 2]);
        }
    }

    const int q = lane & 3;
    const int rb = lane >> 2;
#pragma unroll
    for (int nt = 0; nt < 4; nt++) {
        int col = n0 + wn * 32 + nt * 8 + q * 2;
        float2 bv = *(const float2*)(bias + col);
#pragma unroll
        for (int mt = 0; mt < 4; mt++) {
            int r = m0 + wm * 64 + mt * 16 + rb;
            if (r < M) {
                float2 o = make_float2(acc[mt][nt][0] + bv.x, acc[mt][nt][1] + bv.y);
                *(float2*)(C + (size_t)r * N + col) = o;
            }
            if (r + 8 < M) {
                float2 o = make_float2(acc[mt][nt][2] + bv.x, acc[mt][nt][3] + bv.y);
                *(float2*)(C + (size_t)(r + 8) * N + col) = o;
            }
        }
    }
}

// ---------------------------------------------------------------------------
// Fused RMSNorm + RoPE; reads fp32, writes fp16.
// ---------------------------------------------------------------------------
__global__ __launch_bounds__(256) void rms_rope(
    const float* __restrict__ y, __half* __restrict__ yh,
    const float* __restrict__ g,
    const float* __restrict__ freqs, const int* __restrict__ grid_sizes,
    int L, int dim, int c, int c0, int c1)
{
    const int l = blockIdx.x;
    const float* row = y + (size_t)l * dim;
    __half* rowh = yh + (size_t)l * dim;

    float s = 0.f;
    for (int i = threadIdx.x; i < dim; i += blockDim.x) {
        float v = row[i];
        s += v * v;
    }
#pragma unroll
    for (int off = 16; off; off >>= 1)
        s += __shfl_down_sync(0xffffffffu, s, off);

    __shared__ float red[9];
    int warp = threadIdx.x >> 5, lane = threadIdx.x & 31;
    if (lane == 0) red[warp] = s;
    __syncthreads();
    if (threadIdx.x == 0) {
        float t = 0.f;
        for (int i = 0; i < 8; i++) t += red[i];
        red[8] = t;
    }
    __syncthreads();
    const float rs = rsqrtf(red[8] / (float)dim + 1e-6f);

    const int gf = grid_sizes[0], gh = grid_sizes[1], gw = grid_sizes[2];
    const int sl = gf * gh * gw;
    const bool rot = (l < sl);
    int fi = 0, hi = 0, wi = 0;
    if (rot) {
        fi = l / (gh * gw);
        int rem = l - fi * gh * gw;
        hi = rem / gw;
        wi = rem - hi * gw;
    }

    const int half = dim >> 1;
    for (int p = threadIdx.x; p < half; p += blockDim.x) {
        int head = p / c;
        int j = p - head * c;
        int i0 = head * 2 * c + 2 * j;
        float a = row[i0] * rs * g[i0];
        float b = row[i0 + 1] * rs * g[i0 + 1];
        float o0 = a, o1 = b;
        if (rot) {
            int pos = (j < c0) ? fi : ((j < c0 + c1) ? hi : wi);
            float ang = freqs[pos * c + j];
            float sn, cs;
            sincosf(ang, &sn, &cs);
            o0 = a * cs - b * sn;
            o1 = a * sn + b * cs;
        }
        *(__half2*)(rowh + i0) = __floats2half2_rn(o0, o1);
    }
}

// ---------------------------------------------------------------------------
// fp16 flash attention: 128 q rows x 1 head per CTA, 8 warps (16 q rows each).
// cp.async double-buffered 64-key K/V tiles; Q staged through the K buffers.
// ldmatrix.trans for V; P->A fragment lane-identity. Output fp16.
// ---------------------------------------------------------------------------
#define LDK 136

__global__ __launch_bounds__(256) void attn_f16(
    const __half* __restrict__ qg, const __half* __restrict__ kg,
    const __half* __restrict__ vg, __half* __restrict__ og,
    int L, int nh, const int* __restrict__ seq_lens)
{
    extern __shared__ __align__(16) __half smh[];
    __half* ksp[2] = { smh,                smh + 64 * LDK };
    __half* vsp[2] = { smh + 2 * 64 * LDK, smh + 3 * 64 * LDK };

    const int tid = threadIdx.x;
    const int wid = tid >> 5;
    const int lane = tid & 31;
    const int q = lane & 3;
    const int rb = lane >> 2;
    const int head = blockIdx.y;
    const int q0 = blockIdx.x << 7;
    const int hoff = head * 128;
    const size_t stride = (size_t)nh * 128;
    const int seqlen = seq_lens[0];
    const float scale = rsqrtf(128.0f);

    const int lrA = (lane & 7) + ((lane >> 3) & 1) * 8;
    const int lcA = (lane >> 4) * 8;
    const int lrB = (lane & 7) + ((lane >> 4) << 3);
    const int lcB = ((lane >> 3) & 1) * 8;
    const int trow = lane & 15;
    const int tcol = (lane >> 4) << 3;

    const uint32_t smb = (uint32_t)__cvta_generic_to_shared(smh);
    const uint32_t ksb[2] = { smb, smb + 64 * LDK * 2 };
    const uint32_t vsb[2] = { smb + 2 * 64 * LDK * 2, smb + 3 * 64 * LDK * 2 };

    const int nkt = (seqlen + 63) >> 6;

    auto stage_kv = [&](int t) {
        const int buf = t & 1;
        const int kbase = t << 6;
#pragma unroll
        for (int it = 0; it < 4; it++) {
            int idx = tid + it * 256;
            int row = idx >> 4;
            int ch = idx & 15;
            int gr = kbase + row;
            int sz = (gr < L) ? 16 : 0;
            size_t goff = (size_t)gr * stride + hoff + ch * 8;
            uint32_t so = (uint32_t)(row * LDK + ch * 8) * 2;
            cpa16(ksb[buf] + so, kg + goff, sz);
            cpa16(vsb[buf] + so, vg + goff, sz);
        }
        cpa_commit();
    };

    // ---- stage Q (128 rows) through the two contiguous K buffers ----
#pragma unroll
    for (int it = 0; it < 8; it++) {
        int idx = tid + it * 256;
        int row = idx >> 4;
        int ch = idx & 15;
        int gr = q0 + row;
        int sz = (gr < L) ? 16 : 0;
        cpa16(smb + (uint32_t)(row * LDK + ch * 8) * 2,
              qg + (size_t)gr * stride + hoff + ch * 8, sz);
    }
    cpa_commit();
    asm volatile("cp.async.wait_group 0;" ::: "memory");
    __syncthreads();

    uint32_t qf[8][4];
#pragma unroll
    for (int ks = 0; ks < 8; ks++)
        ldsm4h(qf[ks], &smh[(wid * 16 + lrA) * LDK + ks * 16 + lcA]);
    __syncthreads();

    float o[16][4];
#pragma unroll
    for (int nt = 0; nt < 16; nt++)
#pragma unroll
        for (int i = 0; i < 4; i++) o[nt][i] = 0.f;
    float m_r[2] = {-1e30f, -1e30f};
    float l_r[2] = {0.f, 0.f};

    stage_kv(0);

    for (int t = 0; t < nkt; t++) {
        const int buf = t & 1;
        const int kbase = t << 6;
        const __half* Ks = ksp[buf];
        const __half* Vs = vsp[buf];

        if (t + 1 < nkt) {
            stage_kv(t + 1);
            asm volatile("cp.async.wait_group 1;" ::: "memory");
        } else {
            asm volatile("cp.async.wait_group 0;" ::: "memory");
        }
        __syncthreads();

        // ---- S = Q K^T ----
        float s[8][4];
#pragma unroll
        for (int nt = 0; nt < 8; nt++)
#pragma unroll
            for (int i = 0; i < 4; i++) s[nt][i] = 0.f;

#pragma unroll
        for (int ks = 0; ks < 8; ks++) {
#pragma unroll
            for (int np = 0; np < 4; np++) {
                uint32_t bf[4];
                ldsm4h(bf, &Ks[(np * 16 + lrB) * LDK + ks * 16 + lcB]);
                mma_f16(s[2 * np], qf[ks], bf);
                mma_f16(s[2 * np + 1], qf[ks], bf + 2);
            }
        }

        // ---- scale + mask ----
#pragma unroll
        for (int nt = 0; nt < 8; nt++) {
            int col = kbase + nt * 8 + 2 * q;
            s[nt][0] = (col     < seqlen) ? s[nt][0] * scale : -1e30f;
            s[nt][2] = (col     < seqlen) ? s[nt][2] * scale : -1e30f;
            s[nt][1] = (col + 1 < seqlen) ? s[nt][1] * scale : -1e30f;
            s[nt][3] = (col + 1 < seqlen) ? s[nt][3] * scale : -1e30f;
        }

        // ---- online softmax ----
#pragma unroll
        for (int r = 0; r < 2; r++) {
            float mx = -1e30f;
#pragma unroll
            for (int nt = 0; nt < 8; nt++)
                mx = fmaxf(mx, fmaxf(s[nt][2 * r], s[nt][2 * r + 1]));
            mx = fmaxf(mx, __shfl_xor_sync(0xffffffffu, mx, 1));
            mx = fmaxf(mx, __shfl_xor_sync(0xffffffffu, mx, 2));
            float mn = fmaxf(m_r[r], mx);
            float cf = __expf(m_r[r] - mn);
            m_r[r] = mn;
            float sum = 0.f;
#pragma unroll
            for (int nt = 0; nt < 8; nt++) {
                float p0 = __expf(s[nt][2 * r] - mn);
                float p1 = __expf(s[nt][2 * r + 1] - mn);
                s[nt][2 * r] = p0;
                s[nt][2 * r + 1] = p1;
                sum += p0 + p1;
            }
            sum += __shfl_xor_sync(0xffffffffu, sum, 1);
            sum += __shfl_xor_sync(0xffffffffu, sum, 2);
            l_r[r] = l_r[r] * cf + sum;
#pragma unroll
            for (int nt = 0; nt < 16; nt++) {
                o[nt][2 * r] *= cf;
                o[nt][2 * r + 1] *= cf;
            }
        }

        // ---- O += P V ----
#pragma unroll
        for (int kt = 0; kt < 4; kt++) {
            uint32_t aP[4];
            aP[0] = packh2(s[2 * kt][0], s[2 * kt][1]);
            aP[1] = packh2(s[2 * kt][2], s[2 * kt][3]);
            aP[2] = packh2(s[2 * kt + 1][0], s[2 * kt + 1][1]);
            aP[3] = packh2(s[2 * kt + 1][2], s[2 * kt + 1][3]);
            const __half* vrow = &Vs[(kt * 16 + trow) * LDK + tcol];
#pragma unroll
            for (int np = 0; np < 8; np++) {
                uint32_t bf[4];
                ldsm4t(bf, vrow + np * 16);
                mma_f16(o[2 * np], aP, bf);
                mma_f16(o[2 * np + 1], aP, bf + 2);
            }
        }
        __syncthreads();
    }

    // ---- normalize + store (fp16) ----
    float inv0 = 1.0f / l_r[0];
    float inv1 = 1.0f / l_r[1];
    int r = q0 + wid * 16 + rb;
#pragma unroll
    for (int nt = 0; nt < 16; nt++) {
        int col = hoff + nt * 8 + 2 * q;
        if (r < L)
            *(__half2*)(og + (size_t)r * stride + col) =
                __floats2half2_rn(o[nt][0] * inv0, o[nt][1] * inv0);
        if (r + 8 < L)
            *(__half2*)(og + (size_t)(r + 8) * stride + col) =
                __floats2half2_rn(o[nt][2] * inv1, o[nt][3] * inv1);
    }
}

// ---------------------------------------------------------------------------
// kernel_launch
// ---------------------------------------------------------------------------
extern "C" void kernel_launch(void* const* d_in, const int* in_sizes, int n_in,
                              void* d_out, int out_size)
{
    (void)n_in; (void)out_size;
    const float* x          = (const float*)d_in[0];
    const int*   seq_lens   = (const int*)d_in[1];
    const int*   grid_sizes = (const int*)d_in[2];
    const float* freqs      = (const float*)d_in[3];
    const float* Wq = (const float*)d_in[4];
    const float* bq = (const float*)d_in[5];
    const float* Wk = (const float*)d_in[6];
    const float* bk = (const float*)d_in[7];
    const float* Wv = (const float*)d_in[8];
    const float* bv = (const float*)d_in[9];
    const float* Wo = (const float*)d_in[10];
    const float* bo = (const float*)d_in[11];
    const float* gq = (const float*)d_in[12];
    const float* gk = (const float*)d_in[13];
    float* out = (float*)d_out;

    const int dim = in_sizes[5];             // 1536
    const int L   = in_sizes[0] / dim;       // 5000
    const int c   = in_sizes[3] / 1024;      // 64
    const int d   = 2 * c;                   // 128
    const int nh  = dim / d;                 // 12
    const int c1  = c / 3;                   // 21
    const int c0  = c - 2 * c1;              // 22

    float *qp, *kp, *vp;
    __half *xh, *qh, *kh, *vh, *oh, *wqt, *wkt, *wvt, *wot;
    cudaGetSymbolAddress((void**)&qp, g_q);
    cudaGetSymbolAddress((void**)&kp, g_k);
    cudaGetSymbolAddress((void**)&vp, g_v);
    cudaGetSymbolAddress((void**)&xh, g_xh);
    cudaGetSymbolAddress((void**)&qh, g_qh);
    cudaGetSymbolAddress((void**)&kh, g_kh);
    cudaGetSymbolAddress((void**)&vh, g_vh);
    cudaGetSymbolAddress((void**)&oh, g_oh);
    cudaGetSymbolAddress((void**)&wqt, g_wq);
    cudaGetSymbolAddress((void**)&wkt, g_wk);
    cudaGetSymbolAddress((void**)&wvt, g_wv);
    cudaGetSymbolAddress((void**)&wot, g_wo);

    // ---- prep: half conversions + weight transposes ----
    f2h<<<(L * dim + 1023) / 1024, 256>>>(x, xh, L * dim);
    dim3 tgrid(dim / 32, dim / 32);
    transpose_h<<<tgrid, 256>>>(Wq, wqt, dim, dim);
    transpose_h<<<tgrid, 256>>>(Wk, wkt, dim, dim);
    transpose_h<<<tgrid, 256>>>(Wv, wvt, dim, dim);
    transpose_h<<<tgrid, 256>>>(Wo, wot, dim, dim);

    dim3 gblk(dim / 128, (L + 127) / 128);
    dim3 tblk(256);

    gemm_hh<<<gblk, tblk>>>(xh, wqt, bq, qp, L, dim, dim);
    gemm_hh<<<gblk, tblk>>>(xh, wkt, bk, kp, L, dim, dim);
    gemm_hh<<<gblk, tblk>>>(xh, wvt, bv, vp, L, dim, dim);

    rms_rope<<<L, 256>>>(qp, qh, gq, freqs, grid_sizes, L, dim, c, c0, c1);
    rms_rope<<<L, 256>>>(kp, kh, gk, freqs, grid_sizes, L, dim, c, c0, c1);
    f2h<<<(L * dim + 1023) / 1024, 256>>>(vp, vh, L * dim);

    const int attn_smem = 4 * 64 * LDK * (int)sizeof(__half);  // 69632
    cudaFuncSetAttribute(attn_f16, cudaFuncAttributeMaxDynamicSharedMemorySize,
                         attn_smem);
    dim3 fgrid((L + 127) / 128, nh);
    attn_f16<<<fgrid, 256, attn_smem>>>(qh, kh, vh, oh, L, nh, seq_lens);

    gemm_hh<<<gblk, tblk>>>(oh, wot, bo, out, L, dim, dim);
}

// round 13
// speedup vs baseline: 7.1797x; 1.2540x over previous
#include <cuda_runtime.h>
#include <cuda_fp16.h>
#include <math.h>
#include <stdint.h>

// ---------------------------------------------------------------------------
// Scratch buffers (device globals; no allocation allowed)
// ---------------------------------------------------------------------------
#define MAX_L   5000
#define DIMM    1536
__device__ float  g_q[MAX_L * DIMM];
__device__ float  g_k[MAX_L * DIMM];
__device__ float  g_v[MAX_L * DIMM];
__device__ __half g_xh[MAX_L * DIMM];
__device__ __half g_qh[MAX_L * DIMM];
__device__ __half g_kh[MAX_L * DIMM];
__device__ __half g_vh[MAX_L * DIMM];
__device__ __half g_oh[MAX_L * DIMM];
__device__ __half g_wq[DIMM * DIMM];
__device__ __half g_wk[DIMM * DIMM];
__device__ __half g_wv[DIMM * DIMM];
__device__ __half g_wo[DIMM * DIMM];

// ---------------------------------------------------------------------------
// Helpers
// ---------------------------------------------------------------------------
__device__ __forceinline__ uint32_t packh2(float a, float b) {
    __half2 h = __floats2half2_rn(a, b);
    return *(uint32_t*)&h;
}

__device__ __forceinline__ void ldsm4h(uint32_t* r, const __half* p) {
    uint32_t a = (uint32_t)__cvta_generic_to_shared(p);
    asm volatile("ldmatrix.sync.aligned.m8n8.x4.shared.b16 {%0,%1,%2,%3}, [%4];"
                 : "=r"(r[0]), "=r"(r[1]), "=r"(r[2]), "=r"(r[3]) : "r"(a));
}

__device__ __forceinline__ void ldsm4t(uint32_t* r, const __half* p) {
    uint32_t a = (uint32_t)__cvta_generic_to_shared(p);
    asm volatile(
        "ldmatrix.sync.aligned.m8n8.x4.trans.shared.b16 {%0,%1,%2,%3}, [%4];"
        : "=r"(r[0]), "=r"(r[1]), "=r"(r[2]), "=r"(r[3]) : "r"(a));
}

__device__ __forceinline__ void mma_f16(float* d, const uint32_t* a,
                                        const uint32_t* b) {
    asm volatile(
        "mma.sync.aligned.m16n8k16.row.col.f32.f16.f16.f32 "
        "{%0,%1,%2,%3}, {%4,%5,%6,%7}, {%8,%9}, {%0,%1,%2,%3};"
        : "+f"(d[0]), "+f"(d[1]), "+f"(d[2]), "+f"(d[3])
        : "r"(a[0]), "r"(a[1]), "r"(a[2]), "r"(a[3]), "r"(b[0]), "r"(b[1]));
}

__device__ __forceinline__ void cpa16(uint32_t dst, const void* src, int sz) {
    asm volatile("cp.async.cg.shared.global [%0], [%1], 16, %2;"
                 :: "r"(dst), "l"(src), "r"(sz) : "memory");
}
__device__ __forceinline__ void cpa_commit() {
    asm volatile("cp.async.commit_group;" ::: "memory");
}

// ---------------------------------------------------------------------------
// Prep: fp32 -> fp16 convert
// ---------------------------------------------------------------------------
__global__ __launch_bounds__(256) void f2h(const float* __restrict__ src,
                                           __half* __restrict__ dst, int n)
{
    int i = (blockIdx.x * 256 + threadIdx.x) * 4;
    if (i < n) {
        float4 v = *(const float4*)(src + i);
        uint2 t;
        t.x = packh2(v.x, v.y);
        t.y = packh2(v.z, v.w);
        *(uint2*)(dst + i) = t;
    }
}

// ---------------------------------------------------------------------------
// Prep: all 4 weight transposes in one launch (z selects matrix)
// W[K][N] fp32 -> Wt[N][K] fp16
// ---------------------------------------------------------------------------
__global__ __launch_bounds__(256) void transpose_all(
    const float* __restrict__ W0, const float* __restrict__ W1,
    const float* __restrict__ W2, const float* __restrict__ W3,
    __half* __restrict__ T0, __half* __restrict__ T1,
    __half* __restrict__ T2, __half* __restrict__ T3, int K, int N)
{
    const float* W = (blockIdx.z == 0) ? W0 : (blockIdx.z == 1) ? W1
                   : (blockIdx.z == 2) ? W2 : W3;
    __half* Wt = (blockIdx.z == 0) ? T0 : (blockIdx.z == 1) ? T1
               : (blockIdx.z == 2) ? T2 : T3;

    __shared__ float t[32][33];
    const int tx = threadIdx.x & 31;
    const int ty = threadIdx.x >> 5;
    const int n0 = blockIdx.x << 5;
    const int k0 = blockIdx.y << 5;
#pragma unroll
    for (int i = 0; i < 4; i++)
        t[ty + 8 * i][tx] = W[(size_t)(k0 + ty + 8 * i) * N + n0 + tx];
    __syncthreads();
#pragma unroll
    for (int i = 0; i < 4; i++)
        Wt[(size_t)(n0 + ty + 8 * i) * K + k0 + tx] =
            __float2half_rn(t[tx][ty + 8 * i]);
}

// ---------------------------------------------------------------------------
// all-fp16 GEMM body: C[M,N] = A[M,K] @ Wt[N,K]^T + bias
// 128x128x32 tile, 8 warps, m16n8k16, cp.async 2-stage pipeline.
// ---------------------------------------------------------------------------
#define GLDH 40
#define GSTAGE (128 * GLDH)   // halves per stage buffer

__device__ __forceinline__ void gemm_body(
    const __half* __restrict__ A, const __half* __restrict__ Wt,
    const float* __restrict__ bias, float* __restrict__ C,
    int M, int N, int K, __half* As, __half* Bs)
{
    const int tid = threadIdx.x;
    const int wid = tid >> 5;
    const int lane = tid & 31;
    const int wm = wid >> 2;
    const int wn = wid & 3;
    const int m0 = blockIdx.y << 7;
    const int n0 = blockIdx.x << 7;

    const int lrA = (lane & 7) + ((lane >> 3) & 1) * 8;
    const int lcA = (lane >> 4) * 8;
    const int lrB = (lane & 7) + ((lane >> 4) << 3);
    const int lcB = ((lane >> 3) & 1) * 8;

    const uint32_t asb = (uint32_t)__cvta_generic_to_shared(As);
    const uint32_t bsb = (uint32_t)__cvta_generic_to_shared(Bs);

    float acc[4][4][4];
#pragma unroll
    for (int mt = 0; mt < 4; mt++)
#pragma unroll
        for (int nt = 0; nt < 4; nt++)
#pragma unroll
            for (int i = 0; i < 4; i++) acc[mt][nt][i] = 0.f;

    const int NS = K >> 5;

    auto stage = [&](int s) {
        const int buf = s & 1;
        const int k0 = s << 5;
        const uint32_t ab = asb + buf * GSTAGE * 2;
        const uint32_t bb = bsb + buf * GSTAGE * 2;
#pragma unroll
        for (int it = 0; it < 2; it++) {
            int idx = tid + it * 256;          // 0..511
            int row = idx >> 2;
            int ch = idx & 3;
            uint32_t so = (uint32_t)(row * GLDH + ch * 8) * 2;
            int gr = m0 + row;
            int sz = (gr < M) ? 16 : 0;
            cpa16(ab + so, A + (size_t)gr * K + k0 + ch * 8, sz);
            cpa16(bb + so, Wt + (size_t)(n0 + row) * K + k0 + ch * 8, 16);
        }
        cpa_commit();
    };

    stage(0);

    for (int s = 0; s < NS; s++) {
        asm volatile("cp.async.wait_group 0;" ::: "memory");
        __syncthreads();
        if (s + 1 < NS) stage(s + 1);

        const __half* Ab = As + (s & 1) * GSTAGE;
        const __half* Bb = Bs + (s & 1) * GSTAGE;
#pragma unroll
        for (int ks = 0; ks < 2; ks++) {
            uint32_t af[4][4], bf[2][4];
#pragma unroll
            for (int mt = 0; mt < 4; mt++)
                ldsm4h(af[mt], &Ab[(wm * 64 + mt * 16 + lrA) * GLDH + ks * 16 + lcA]);
#pragma unroll
            for (int np = 0; np < 2; np++)
                ldsm4h(bf[np], &Bb[(wn * 32 + np * 16 + lrB) * GLDH + ks * 16 + lcB]);
#pragma unroll
            for (int mt = 0; mt < 4; mt++)
#pragma unroll
                for (int nt = 0; nt < 4; nt++)
                    mma_f16(acc[mt][nt], af[mt], &bf[nt >> 1][(nt & 1) * 2]);
        }
        __syncthreads();
    }

    const int q = lane & 3;
    const int rb = lane >> 2;
#pragma unroll
    for (int nt = 0; nt < 4; nt++) {
        int col = n0 + wn * 32 + nt * 8 + q * 2;
        float2 bv = *(const float2*)(bias + col);
#pragma unroll
        for (int mt = 0; mt < 4; mt++) {
            int r = m0 + wm * 64 + mt * 16 + rb;
            if (r < M) {
                float2 o = make_float2(acc[mt][nt][0] + bv.x, acc[mt][nt][1] + bv.y);
                *(float2*)(C + (size_t)r * N + col) = o;
            }
            if (r + 8 < M) {
                float2 o = make_float2(acc[mt][nt][2] + bv.x, acc[mt][nt][3] + bv.y);
                *(float2*)(C + (size_t)(r + 8) * N + col) = o;
            }
        }
    }
}

// Fused QKV GEMM: blockIdx.z selects (Wq,bq,q) / (Wk,bk,k) / (Wv,bv,v)
__global__ __launch_bounds__(256, 2) void qkv_gemm(
    const __half* __restrict__ A,
    const __half* __restrict__ wq, const __half* __restrict__ wk,
    const __half* __restrict__ wv,
    const float* __restrict__ bq, const float* __restrict__ bk,
    const float* __restrict__ bv,
    float* __restrict__ q, float* __restrict__ k, float* __restrict__ v,
    int M, int N, int K)
{
    extern __shared__ __align__(16) __half gsm[];
    const __half* W = (blockIdx.z == 0) ? wq : (blockIdx.z == 1) ? wk : wv;
    const float* b  = (blockIdx.z == 0) ? bq : (blockIdx.z == 1) ? bk : bv;
    float* C        = (blockIdx.z == 0) ? q  : (blockIdx.z == 1) ? k  : v;
    gemm_body(A, W, b, C, M, N, K, gsm, gsm + 2 * GSTAGE);
}

__global__ __launch_bounds__(256, 2) void out_gemm(
    const __half* __restrict__ A, const __half* __restrict__ Wt,
    const float* __restrict__ bias, float* __restrict__ C,
    int M, int N, int K)
{
    extern __shared__ __align__(16) __half gsm[];
    gemm_body(A, Wt, bias, C, M, N, K, gsm, gsm + 2 * GSTAGE);
}

// ---------------------------------------------------------------------------
// Fused post-QKV: z=0 rms+rope(q), z=1 rms+rope(k), z=2 f2h(v).
// One block per row.
// ---------------------------------------------------------------------------
__global__ __launch_bounds__(256) void qkv_post(
    const float* __restrict__ q, const float* __restrict__ k,
    const float* __restrict__ v,
    __half* __restrict__ qh, __half* __restrict__ kh, __half* __restrict__ vh,
    const float* __restrict__ gq, const float* __restrict__ gk,
    const float* __restrict__ freqs, const int* __restrict__ grid_sizes,
    int L, int dim, int c, int c0, int c1)
{
    const int z = blockIdx.y;
    const int l = blockIdx.x;

    if (z == 2) {
        const float* row = v + (size_t)l * dim;
        __half* rowh = vh + (size_t)l * dim;
        for (int idx = threadIdx.x; idx < (dim >> 2); idx += 256) {
            float4 t = *(const float4*)(row + idx * 4);
            uint2 u;
            u.x = packh2(t.x, t.y);
            u.y = packh2(t.z, t.w);
            *(uint2*)(rowh + idx * 4) = u;
        }
        return;
    }

    const float* row = ((z == 0) ? q : k) + (size_t)l * dim;
    __half* rowh = ((z == 0) ? qh : kh) + (size_t)l * dim;
    const float* g = (z == 0) ? gq : gk;

    float s = 0.f;
    for (int i = threadIdx.x; i < dim; i += blockDim.x) {
        float vv = row[i];
        s += vv * vv;
    }
#pragma unroll
    for (int off = 16; off; off >>= 1)
        s += __shfl_down_sync(0xffffffffu, s, off);

    __shared__ float red[9];
    int warp = threadIdx.x >> 5, lane = threadIdx.x & 31;
    if (lane == 0) red[warp] = s;
    __syncthreads();
    if (threadIdx.x == 0) {
        float t = 0.f;
        for (int i = 0; i < 8; i++) t += red[i];
        red[8] = t;
    }
    __syncthreads();
    const float rs = rsqrtf(red[8] / (float)dim + 1e-6f);

    const int gf = grid_sizes[0], gh = grid_sizes[1], gw = grid_sizes[2];
    const int sl = gf * gh * gw;
    const bool rot = (l < sl);
    int fi = 0, hi = 0, wi = 0;
    if (rot) {
        fi = l / (gh * gw);
        int rem = l - fi * gh * gw;
        hi = rem / gw;
        wi = rem - hi * gw;
    }

    const int half = dim >> 1;
    for (int p = threadIdx.x; p < half; p += blockDim.x) {
        int head = p / c;
        int j = p - head * c;
        int i0 = head * 2 * c + 2 * j;
        float a = row[i0] * rs * g[i0];
        float b = row[i0 + 1] * rs * g[i0 + 1];
        float o0 = a, o1 = b;
        if (rot) {
            int pos = (j < c0) ? fi : ((j < c0 + c1) ? hi : wi);
            float ang = freqs[pos * c + j];
            float sn, cs;
            sincosf(ang, &sn, &cs);
            o0 = a * cs - b * sn;
            o1 = a * sn + b * cs;
        }
        *(__half2*)(rowh + i0) = __floats2half2_rn(o0, o1);
    }
}

// ---------------------------------------------------------------------------
// fp16 flash attention: 128 q rows x 1 head per CTA, 8 warps.
// cp.async double-buffered 64-key K/V tiles; ldmatrix.trans for V;
// exp2-based online softmax (scale*log2e folded in). Output fp16.
// ---------------------------------------------------------------------------
#define LDK 136

__global__ __launch_bounds__(256) void attn_f16(
    const __half* __restrict__ qg, const __half* __restrict__ kg,
    const __half* __restrict__ vg, __half* __restrict__ og,
    int L, int nh, const int* __restrict__ seq_lens)
{
    extern __shared__ __align__(16) __half smh[];
    __half* ksp[2] = { smh,                smh + 64 * LDK };
    __half* vsp[2] = { smh + 2 * 64 * LDK, smh + 3 * 64 * LDK };

    const int tid = threadIdx.x;
    const int wid = tid >> 5;
    const int lane = tid & 31;
    const int q = lane & 3;
    const int rb = lane >> 2;
    const int head = blockIdx.y;
    const int q0 = blockIdx.x << 7;
    const int hoff = head * 128;
    const size_t stride = (size_t)nh * 128;
    const int seqlen = seq_lens[0];
    const float scale2 = rsqrtf(128.0f) * 1.4426950408889634f;  // *log2(e)

    const int lrA = (lane & 7) + ((lane >> 3) & 1) * 8;
    const int lcA = (lane >> 4) * 8;
    const int lrB = (lane & 7) + ((lane >> 4) << 3);
    const int lcB = ((lane >> 3) & 1) * 8;
    const int trow = lane & 15;
    const int tcol = (lane >> 4) << 3;

    const uint32_t smb = (uint32_t)__cvta_generic_to_shared(smh);
    const uint32_t ksb[2] = { smb, smb + 64 * LDK * 2 };
    const uint32_t vsb[2] = { smb + 2 * 64 * LDK * 2, smb + 3 * 64 * LDK * 2 };

    const int nkt = (seqlen + 63) >> 6;

    auto stage_kv = [&](int t) {
        const int buf = t & 1;
        const int kbase = t << 6;
#pragma unroll
        for (int it = 0; it < 4; it++) {
            int idx = tid + it * 256;
            int row = idx >> 4;
            int ch = idx & 15;
            int gr = kbase + row;
            int sz = (gr < L) ? 16 : 0;
            size_t goff = (size_t)gr * stride + hoff + ch * 8;
            uint32_t so = (uint32_t)(row * LDK + ch * 8) * 2;
            cpa16(ksb[buf] + so, kg + goff, sz);
            cpa16(vsb[buf] + so, vg + goff, sz);
        }
        cpa_commit();
    };

    // ---- stage Q (128 rows) through the two contiguous K buffers ----
#pragma unroll
    for (int it = 0; it < 8; it++) {
        int idx = tid + it * 256;
        int row = idx >> 4;
        int ch = idx & 15;
        int gr = q0 + row;
        int sz = (gr < L) ? 16 : 0;
        cpa16(smb + (uint32_t)(row * LDK + ch * 8) * 2,
              qg + (size_t)gr * stride + hoff + ch * 8, sz);
    }
    cpa_commit();
    asm volatile("cp.async.wait_group 0;" ::: "memory");
    __syncthreads();

    uint32_t qf[8][4];
#pragma unroll
    for (int ks = 0; ks < 8; ks++)
        ldsm4h(qf[ks], &smh[(wid * 16 + lrA) * LDK + ks * 16 + lcA]);
    __syncthreads();

    float o[16][4];
#pragma unroll
    for (int nt = 0; nt < 16; nt++)
#pragma unroll
        for (int i = 0; i < 4; i++) o[nt][i] = 0.f;
    float m_r[2] = {-1e30f, -1e30f};
    float l_r[2] = {0.f, 0.f};

    stage_kv(0);

    for (int t = 0; t < nkt; t++) {
        const int buf = t & 1;
        const int kbase = t << 6;
        const __half* Ks = ksp[buf];
        const __half* Vs = vsp[buf];

        if (t + 1 < nkt) {
            stage_kv(t + 1);
            asm volatile("cp.async.wait_group 1;" ::: "memory");
        } else {
            asm volatile("cp.async.wait_group 0;" ::: "memory");
        }
        __syncthreads();

        // ---- S = Q K^T ----
        float s[8][4];
#pragma unroll
        for (int nt = 0; nt < 8; nt++)
#pragma unroll
            for (int i = 0; i < 4; i++) s[nt][i] = 0.f;

#pragma unroll
        for (int ks = 0; ks < 8; ks++) {
#pragma unroll
            for (int np = 0; np < 4; np++) {
                uint32_t bf[4];
                ldsm4h(bf, &Ks[(np * 16 + lrB) * LDK + ks * 16 + lcB]);
                mma_f16(s[2 * np], qf[ks], bf);
                mma_f16(s[2 * np + 1], qf[ks], bf + 2);
            }
        }

        // ---- scale (base-2) + mask ----
#pragma unroll
        for (int nt = 0; nt < 8; nt++) {
            int col = kbase + nt * 8 + 2 * q;
            s[nt][0] = (col     < seqlen) ? s[nt][0] * scale2 : -1e30f;
            s[nt][2] = (col     < seqlen) ? s[nt][2] * scale2 : -1e30f;
            s[nt][1] = (col + 1 < seqlen) ? s[nt][1] * scale2 : -1e30f;
            s[nt][3] = (col + 1 < seqlen) ? s[nt][3] * scale2 : -1e30f;
        }

        // ---- online softmax (base 2) ----
#pragma unroll
        for (int r = 0; r < 2; r++) {
            float mx = -1e30f;
#pragma unroll
            for (int nt = 0; nt < 8; nt++)
                mx = fmaxf(mx, fmaxf(s[nt][2 * r], s[nt][2 * r + 1]));
            mx = fmaxf(mx, __shfl_xor_sync(0xffffffffu, mx, 1));
            mx = fmaxf(mx, __shfl_xor_sync(0xffffffffu, mx, 2));
            float mn = fmaxf(m_r[r], mx);
            float cf = exp2f(m_r[r] - mn);
            m_r[r] = mn;
            float sum = 0.f;
#pragma unroll
            for (int nt = 0; nt < 8; nt++) {
                float p0 = exp2f(s[nt][2 * r] - mn);
                float p1 = exp2f(s[nt][2 * r + 1] - mn);
                s[nt][2 * r] = p0;
                s[nt][2 * r + 1] = p1;
                sum += p0 + p1;
            }
            sum += __shfl_xor_sync(0xffffffffu, sum, 1);
            sum += __shfl_xor_sync(0xffffffffu, sum, 2);
            l_r[r] = l_r[r] * cf + sum;
#pragma unroll
            for (int nt = 0; nt < 16; nt++) {
                o[nt][2 * r] *= cf;
                o[nt][2 * r + 1] *= cf;
            }
        }

        // ---- O += P V ----
#pragma unroll
        for (int kt = 0; kt < 4; kt++) {
            uint32_t aP[4];
            aP[0] = packh2(s[2 * kt][0], s[2 * kt][1]);
            aP[1] = packh2(s[2 * kt][2], s[2 * kt][3]);
            aP[2] = packh2(s[2 * kt + 1][0], s[2 * kt + 1][1]);
            aP[3] = packh2(s[2 * kt + 1][2], s[2 * kt + 1][3]);
            const __half* vrow = &Vs[(kt * 16 + trow) * LDK + tcol];
#pragma unroll
            for (int np = 0; np < 8; np++) {
                uint32_t bf[4];
                ldsm4t(bf, vrow + np * 16);
                mma_f16(o[2 * np], aP, bf);
                mma_f16(o[2 * np + 1], aP, bf + 2);
            }
        }
        __syncthreads();
    }

    // ---- normalize + store (fp16) ----
    float inv0 = 1.0f / l_r[0];
    float inv1 = 1.0f / l_r[1];
    int r = q0 + wid * 16 + rb;
#pragma unroll
    for (int nt = 0; nt < 16; nt++) {
        int col = hoff + nt * 8 + 2 * q;
        if (r < L)
            *(__half2*)(og + (size_t)r * stride + col) =
                __floats2half2_rn(o[nt][0] * inv0, o[nt][1] * inv0);
        if (r + 8 < L)
            *(__half2*)(og + (size_t)(r + 8) * stride + col) =
                __floats2half2_rn(o[nt][2] * inv1, o[nt][3] * inv1);
    }
}

// ---------------------------------------------------------------------------
// kernel_launch
// Launch order puts attn_f16 at 0-based index 4 (the ncu-profiled slot).
// ---------------------------------------------------------------------------
extern "C" void kernel_launch(void* const* d_in, const int* in_sizes, int n_in,
                              void* d_out, int out_size)
{
    (void)n_in; (void)out_size;
    const float* x          = (const float*)d_in[0];
    const int*   seq_lens   = (const int*)d_in[1];
    const int*   grid_sizes = (const int*)d_in[2];
    const float* freqs      = (const float*)d_in[3];
    const float* Wq = (const float*)d_in[4];
    const float* bq = (const float*)d_in[5];
    const float* Wk = (const float*)d_in[6];
    const float* bk = (const float*)d_in[7];
    const float* Wv = (const float*)d_in[8];
    const float* bv = (const float*)d_in[9];
    const float* Wo = (const float*)d_in[10];
    const float* bo = (const float*)d_in[11];
    const float* gq = (const float*)d_in[12];
    const float* gk = (const float*)d_in[13];
    float* out = (float*)d_out;

    const int dim = in_sizes[5];             // 1536
    const int L   = in_sizes[0] / dim;       // 5000
    const int c   = in_sizes[3] / 1024;      // 64
    const int d   = 2 * c;                   // 128
    const int nh  = dim / d;                 // 12
    const int c1  = c / 3;                   // 21
    const int c0  = c - 2 * c1;              // 22

    float *qp, *kp, *vp;
    __half *xh, *qh, *kh, *vh, *oh, *wqt, *wkt, *wvt, *wot;
    cudaGetSymbolAddress((void**)&qp, g_q);
    cudaGetSymbolAddress((void**)&kp, g_k);
    cudaGetSymbolAddress((void**)&vp, g_v);
    cudaGetSymbolAddress((void**)&xh, g_xh);
    cudaGetSymbolAddress((void**)&qh, g_qh);
    cudaGetSymbolAddress((void**)&kh, g_kh);
    cudaGetSymbolAddress((void**)&vh, g_vh);
    cudaGetSymbolAddress((void**)&oh, g_oh);
    cudaGetSymbolAddress((void**)&wqt, g_wq);
    cudaGetSymbolAddress((void**)&wkt, g_wk);
    cudaGetSymbolAddress((void**)&wvt, g_wv);
    cudaGetSymbolAddress((void**)&wot, g_wo);

    const int gemm_smem = 4 * GSTAGE * (int)sizeof(__half);  // 40960
    cudaFuncSetAttribute(qkv_gemm, cudaFuncAttributeMaxDynamicSharedMemorySize,
                         gemm_smem);
    cudaFuncSetAttribute(out_gemm, cudaFuncAttributeMaxDynamicSharedMemorySize,
                         gemm_smem);
    const int attn_smem = 4 * 64 * LDK * (int)sizeof(__half);  // 69632
    cudaFuncSetAttribute(attn_f16, cudaFuncAttributeMaxDynamicSharedMemorySize,
                         attn_smem);

    // 0: all weight transposes
    dim3 tgrid(dim / 32, dim / 32, 4);
    transpose_all<<<tgrid, 256>>>(Wq, Wk, Wv, Wo, wqt, wkt, wvt, wot, dim, dim);

    // 1: x -> half
    f2h<<<(L * dim + 1023) / 1024, 256>>>(x, xh, L * dim);

    // 2: fused QKV GEMM
    dim3 gblk(dim / 128, (L + 127) / 128, 3);
    qkv_gemm<<<gblk, 256, gemm_smem>>>(xh, wqt, wkt, wvt, bq, bk, bv,
                                       qp, kp, vp, L, dim, dim);

    // 3: fused post (rms+rope q/k, convert v)
    dim3 pgrid(L, 3);
    qkv_post<<<pgrid, 256>>>(qp, kp, vp, qh, kh, vh, gq, gk, freqs,
                             grid_sizes, L, dim, c, c0, c1);

    // 4: attention (profiled slot)
    dim3 fgrid((L + 127) / 128, nh);
    attn_f16<<<fgrid, 256, attn_smem>>>(qh, kh, vh, oh, L, nh, seq_lens);

    // 5: output projection
    dim3 oblk(dim / 128, (L + 127) / 128);
    out_gemm<<<oblk, 256, gemm_smem>>>(oh, wot, bo, out, L, dim, dim);
}